// round 2
// baseline (speedup 1.0000x reference)
#include <cuda_runtime.h>
#include <math.h>

#define Bz 64
#define Rr 28
#define Ss 784
#define Cc 256
#define Hh 8
#define DRr 98
#define Ee 128
#define BH 512

// ---------------- scratch (device globals: no runtime allocation) ----------------
__device__ float g_qpool[Bz*Ss*Cc];     // avg-pooled x, [B,S,C]
__device__ float g_kpool[Bz*Ss*Cc];     // max-pooled x, [B,S,C]
__device__ float g_vconv[Bz*Ss*Cc];     // conv out,     [B,S,C]
__device__ float g_vpool[Bz*Ss*Cc];     // pooled conv,  [B,S,C]
__device__ float g_q[BH*Cc*Ee];         // [BH,C,E]
__device__ float g_k[BH*Cc*Ee];         // [BH,C,E]
__device__ float g_scores[(size_t)BH*Cc*Cc]; // [BH,C,C] -> softmaxed in place
__device__ float g_invden[BH*Cc];       // 1/temperature per (bh,c)

// ---------------- pooling: avg (valid-count) + max, SAME ----------------
__global__ __launch_bounds__(256) void pool_qk_kernel(const float* __restrict__ x) {
    int bs = blockIdx.x;                 // b*784 + pix
    int c  = threadIdx.x;
    int b  = bs / 784;
    int pix = bs - b * 784;
    int i = pix / 28, j = pix - i * 28;
    const float* xb = x + (size_t)b * 784 * 256;
    float sum = 0.f, mx = -INFINITY;
    int cnt = 0;
    #pragma unroll
    for (int di = -1; di <= 1; di++) {
        #pragma unroll
        for (int dj = -1; dj <= 1; dj++) {
            int ii = i + di, jj = j + dj;
            if ((unsigned)ii < 28u && (unsigned)jj < 28u) {
                float v = xb[(size_t)(ii * 28 + jj) * 256 + c];
                sum += v;
                mx = fmaxf(mx, v);
                cnt++;
            }
        }
    }
    size_t o = (size_t)bs * 256 + c;
    g_qpool[o] = sum / (float)cnt;
    g_kpool[o] = mx;
}

__global__ __launch_bounds__(256) void pool_v_kernel() {
    int bs = blockIdx.x;
    int c  = threadIdx.x;
    int b  = bs / 784;
    int pix = bs - b * 784;
    int i = pix / 28, j = pix - i * 28;
    const float* xb = g_vconv + (size_t)b * 784 * 256;
    float sum = 0.f;
    int cnt = 0;
    #pragma unroll
    for (int di = -1; di <= 1; di++) {
        #pragma unroll
        for (int dj = -1; dj <= 1; dj++) {
            int ii = i + di, jj = j + dj;
            if ((unsigned)ii < 28u && (unsigned)jj < 28u) {
                sum += xb[(size_t)(ii * 28 + jj) * 256 + c];
                cnt++;
            }
        }
    }
    g_vpool[(size_t)bs * 256 + c] = sum / (float)cnt;
}

// ---------------- 3x3 conv as implicit GEMM: M=50176, N=256, K=2304 ----------------
// block tile 64x64, K-chunk 16, 4x4 per-thread register tile
__global__ __launch_bounds__(256) void conv_kernel(const float* __restrict__ x,
                                                   const float* __restrict__ w,
                                                   const float* __restrict__ bias) {
    __shared__ float As[16][68];   // [k][m]
    __shared__ float Bs[16][68];   // [k][n]
    int t = threadIdx.x;
    int m0 = blockIdx.x << 6, n0 = blockIdx.y << 6;

    // A loader: thread covers row (m0+am), 4 consecutive k (=ci)
    int am = t >> 2, akq = t & 3;
    int m = m0 + am;
    int b = m / 784;
    int pix = m - b * 784;
    int i = pix / 28, j = pix - i * 28;
    const float* xb = x + (size_t)b * 784 * 256;

    // B loader: thread covers k-row (bk), 4 consecutive n
    int bk = t >> 4, bn = (t & 15) << 2;

    int ty = t >> 4, tx = t & 15;
    float acc[4][4];
    #pragma unroll
    for (int a_ = 0; a_ < 4; a_++)
        #pragma unroll
        for (int b_ = 0; b_ < 4; b_++) acc[a_][b_] = 0.f;

    for (int kc = 0; kc < 144; kc++) {
        int tap = kc >> 4;             // 0..8  (di,dj)
        int di = tap / 3, dj = tap - di * 3;
        int ii = i + di - 1, jj = j + dj - 1;
        int ci = ((kc & 15) << 4) + (akq << 2);
        float4 av = make_float4(0.f, 0.f, 0.f, 0.f);
        if ((unsigned)ii < 28u && (unsigned)jj < 28u)
            av = *(const float4*)(xb + ((size_t)(ii * 28 + jj) << 8) + ci);
        float4 bv = *(const float4*)(w + ((size_t)(kc * 16 + bk) << 8) + n0 + bn);
        __syncthreads();
        As[(akq << 2) + 0][am] = av.x;
        As[(akq << 2) + 1][am] = av.y;
        As[(akq << 2) + 2][am] = av.z;
        As[(akq << 2) + 3][am] = av.w;
        *(float4*)&Bs[bk][bn] = bv;
        __syncthreads();
        #pragma unroll
        for (int kk = 0; kk < 16; kk++) {
            float4 a  = *(const float4*)&As[kk][ty << 2];
            float4 b4 = *(const float4*)&Bs[kk][tx << 2];
            float ar[4] = {a.x, a.y, a.z, a.w};
            float br[4] = {b4.x, b4.y, b4.z, b4.w};
            #pragma unroll
            for (int i_ = 0; i_ < 4; i_++)
                #pragma unroll
                for (int j_ = 0; j_ < 4; j_++) acc[i_][j_] += ar[i_] * br[j_];
        }
    }
    float4 bz = *(const float4*)(bias + n0 + (tx << 2));
    #pragma unroll
    for (int i_ = 0; i_ < 4; i_++) {
        int mm = m0 + (ty << 2) + i_;
        float4 r = make_float4(acc[i_][0] + bz.x, acc[i_][1] + bz.y,
                               acc[i_][2] + bz.z, acc[i_][3] + bz.w);
        *(float4*)(g_vconv + ((size_t)mm << 8) + n0 + (tx << 2)) = r;
    }
}

// ---------------- q/k projection: per (b,h) GEMM [256c x 98d] @ [98d x 128e] ----------------
__global__ __launch_bounds__(256) void proj_kernel(const float* __restrict__ wqk,
                                                   const float* __restrict__ bias,
                                                   int which) {
    __shared__ float As[16][68];   // [d][c]
    __shared__ float Bs[16][68];   // [d][e]
    const float* pool = which ? g_kpool : g_qpool;
    float* out = which ? g_k : g_q;
    int t = threadIdx.x;
    int bh = blockIdx.x;
    int b = bh >> 3, h = bh & 7;
    int c0 = blockIdx.y << 6, e0 = blockIdx.z << 6;
    const float* pbase = pool + ((size_t)b * 784 + h * 98) * 256;
    const float* wbase = wqk + (size_t)h * 98 * 128;
    int ld = t >> 4, lc = (t & 15) << 2;
    int ty = t >> 4, tx = t & 15;
    float acc[4][4];
    #pragma unroll
    for (int a_ = 0; a_ < 4; a_++)
        #pragma unroll
        for (int b_ = 0; b_ < 4; b_++) acc[a_][b_] = 0.f;

    for (int kc = 0; kc < 7; kc++) {
        int d = kc * 16 + ld;
        float4 av = make_float4(0.f, 0.f, 0.f, 0.f);
        float4 bv = make_float4(0.f, 0.f, 0.f, 0.f);
        if (d < 98) {
            av = *(const float4*)(pbase + (size_t)d * 256 + c0 + lc);
            bv = *(const float4*)(wbase + (size_t)d * 128 + e0 + lc);
        }
        __syncthreads();
        *(float4*)&As[ld][lc] = av;
        *(float4*)&Bs[ld][lc] = bv;
        __syncthreads();
        #pragma unroll
        for (int kk = 0; kk < 16; kk++) {
            float4 a  = *(const float4*)&As[kk][ty << 2];
            float4 b4 = *(const float4*)&Bs[kk][tx << 2];
            float ar[4] = {a.x, a.y, a.z, a.w};
            float br[4] = {b4.x, b4.y, b4.z, b4.w};
            #pragma unroll
            for (int i_ = 0; i_ < 4; i_++)
                #pragma unroll
                for (int j_ = 0; j_ < 4; j_++) acc[i_][j_] += ar[i_] * br[j_];
        }
    }
    float4 bz = *(const float4*)(bias + h * 128 + e0 + (tx << 2));
    #pragma unroll
    for (int i_ = 0; i_ < 4; i_++) {
        int c = c0 + (ty << 2) + i_;
        float4 r = make_float4(acc[i_][0] + bz.x, acc[i_][1] + bz.y,
                               acc[i_][2] + bz.z, acc[i_][3] + bz.w);
        *(float4*)(out + ((size_t)bh * 256 + c) * 128 + e0 + (tx << 2)) = r;
    }
}

// ---------------- scores: per (b,h) q[256,128] @ k[256,128]^T ----------------
__global__ __launch_bounds__(256) void scores_kernel() {
    __shared__ float As[16][68];   // [e][c]
    __shared__ float Bs[16][68];   // [e][f]
    int t = threadIdx.x;
    int bh = blockIdx.x;
    int c0 = blockIdx.y << 6, f0 = blockIdx.z << 6;
    const float* qb = g_q + (size_t)bh * Cc * Ee;
    const float* kb = g_k + (size_t)bh * Cc * Ee;
    int lr = t >> 2, lq = t & 3;
    int ty = t >> 4, tx = t & 15;
    float acc[4][4];
    #pragma unroll
    for (int a_ = 0; a_ < 4; a_++)
        #pragma unroll
        for (int b_ = 0; b_ < 4; b_++) acc[a_][b_] = 0.f;

    for (int kc = 0; kc < 8; kc++) {
        int e4 = kc * 16 + (lq << 2);
        float4 av = *(const float4*)(qb + (size_t)(c0 + lr) * 128 + e4);
        float4 bv = *(const float4*)(kb + (size_t)(f0 + lr) * 128 + e4);
        __syncthreads();
        As[(lq << 2) + 0][lr] = av.x;
        As[(lq << 2) + 1][lr] = av.y;
        As[(lq << 2) + 2][lr] = av.z;
        As[(lq << 2) + 3][lr] = av.w;
        Bs[(lq << 2) + 0][lr] = bv.x;
        Bs[(lq << 2) + 1][lr] = bv.y;
        Bs[(lq << 2) + 2][lr] = bv.z;
        Bs[(lq << 2) + 3][lr] = bv.w;
        __syncthreads();
        #pragma unroll
        for (int kk = 0; kk < 16; kk++) {
            float4 a  = *(const float4*)&As[kk][ty << 2];
            float4 b4 = *(const float4*)&Bs[kk][tx << 2];
            float ar[4] = {a.x, a.y, a.z, a.w};
            float br[4] = {b4.x, b4.y, b4.z, b4.w};
            #pragma unroll
            for (int i_ = 0; i_ < 4; i_++)
                #pragma unroll
                for (int j_ = 0; j_ < 4; j_++) acc[i_][j_] += ar[i_] * br[j_];
        }
    }
    #pragma unroll
    for (int i_ = 0; i_ < 4; i_++) {
        size_t row = (size_t)bh * 256 + c0 + (ty << 2) + i_;
        *(float4*)(g_scores + row * 256 + f0 + (tx << 2)) =
            make_float4(acc[i_][0], acc[i_][1], acc[i_][2], acc[i_][3]);
    }
}

// ---------------- temperature: rowmean = q·kbar ; p = sigmoid(rowmean @ wp + b) ----------------
__global__ __launch_bounds__(256) void temp_kernel(const float* __restrict__ wp_w,
                                                   const float* __restrict__ wp_b) {
    __shared__ float kbar[128];
    __shared__ float rowmean[256];
    int bh = blockIdx.x;
    int t = threadIdx.x;
    const float* kb = g_k + (size_t)bh * Cc * Ee;
    const float* qb = g_q + (size_t)bh * Cc * Ee;
    if (t < 128) {
        float s = 0.f;
        for (int f = 0; f < 256; f++) s += kb[(size_t)f * 128 + t];
        kbar[t] = s * (1.f / 256.f);
    }
    __syncthreads();
    int w = t >> 5, lane = t & 31;
    float4 kv = *(const float4*)&kbar[lane << 2];
    for (int r = 0; r < 32; r++) {
        int c = (w << 5) + r;
        float4 qv = *(const float4*)(qb + (size_t)c * 128 + (lane << 2));
        float p = qv.x * kv.x + qv.y * kv.y + qv.z * kv.z + qv.w * kv.w;
        #pragma unroll
        for (int o = 16; o; o >>= 1) p += __shfl_xor_sync(0xFFFFFFFFu, p, o);
        if (lane == 0) rowmean[c] = p;
    }
    __syncthreads();
    float s = wp_b[t];
    for (int cc = 0; cc < 256; cc++) s += rowmean[cc] * wp_w[(size_t)cc * 256 + t];
    float sig = 1.f / (1.f + expf(-s));
    // inv_denom = 128^-(0.2+sig) = 2^(-7*(0.2+sig))
    g_invden[(size_t)bh * 256 + t] = exp2f(-7.f * (0.2f + sig));
}

// ---------------- softmax over f with per-row temperature ----------------
__global__ __launch_bounds__(256) void softmax_kernel() {
    __shared__ float red[8];
    int row = blockIdx.x;    // bh*256 + c
    int t = threadIdx.x;
    float invd = g_invden[row];
    float* sp = g_scores + (size_t)row * 256;
    float v = sp[t] * invd;
    float m = v;
    #pragma unroll
    for (int o = 16; o; o >>= 1) m = fmaxf(m, __shfl_xor_sync(0xFFFFFFFFu, m, o));
    if ((t & 31) == 0) red[t >> 5] = m;
    __syncthreads();
    float bm = red[0];
    #pragma unroll
    for (int i = 1; i < 8; i++) bm = fmaxf(bm, red[i]);
    float e = expf(v - bm);
    __syncthreads();
    float s = e;
    #pragma unroll
    for (int o = 16; o; o >>= 1) s += __shfl_xor_sync(0xFFFFFFFFu, s, o);
    if ((t & 31) == 0) red[t >> 5] = s;
    __syncthreads();
    float tot = 0.f;
    #pragma unroll
    for (int i = 0; i < 8; i++) tot += red[i];
    sp[t] = e / tot;
}

// ---------------- att = weights @ v + residual scatter ----------------
// per (b,h): M=256(c), N=98(d), K=256(f). M-tile 64, K-chunk 32
__global__ __launch_bounds__(256) void att_kernel(const float* __restrict__ x,
                                                  float* __restrict__ out) {
    __shared__ float Ash[64][33];  // [c][k]
    __shared__ float Bsh[32][99];  // [k][d]
    int t = threadIdx.x;
    int bh = blockIdx.x;
    int b = bh >> 3, h = bh & 7;
    int c0 = blockIdx.y << 6;
    const float* wrow = g_scores + ((size_t)bh * 256 + c0) * 256;
    const float* vb = g_vpool + ((size_t)b * 784 + h * 98) * 256;
    int tm = t & 31, tn = t >> 5;          // tn in 0..7
    int dd[13];
    #pragma unroll
    for (int r = 0; r < 13; r++) {
        int d = tn + 8 * r;
        dd[r] = (d < 98) ? d : 0;
    }
    float acc[2][13];
    #pragma unroll
    for (int a_ = 0; a_ < 2; a_++)
        #pragma unroll
        for (int r = 0; r < 13; r++) acc[a_][r] = 0.f;

    int ar0 = t >> 3, aq0 = t & 7;
    for (int kc = 0; kc < 8; kc++) {
        int k0 = kc << 5;
        float4 av0 = *(const float4*)(wrow + (size_t)ar0 * 256 + k0 + (aq0 << 2));
        float4 av1 = *(const float4*)(wrow + (size_t)(ar0 + 32) * 256 + k0 + (aq0 << 2));
        float bstage[13];
        #pragma unroll
        for (int it = 0; it < 13; it++) {
            int idx = t + (it << 8);
            if (idx < 3136) {
                int kk = idx & 31, d = idx >> 5;
                bstage[it] = vb[(size_t)d * 256 + k0 + kk];
            }
        }
        __syncthreads();
        Ash[ar0][(aq0 << 2) + 0] = av0.x;
        Ash[ar0][(aq0 << 2) + 1] = av0.y;
        Ash[ar0][(aq0 << 2) + 2] = av0.z;
        Ash[ar0][(aq0 << 2) + 3] = av0.w;
        Ash[ar0 + 32][(aq0 << 2) + 0] = av1.x;
        Ash[ar0 + 32][(aq0 << 2) + 1] = av1.y;
        Ash[ar0 + 32][(aq0 << 2) + 2] = av1.z;
        Ash[ar0 + 32][(aq0 << 2) + 3] = av1.w;
        #pragma unroll
        for (int it = 0; it < 13; it++) {
            int idx = t + (it << 8);
            if (idx < 3136) Bsh[idx & 31][idx >> 5] = bstage[it];
        }
        __syncthreads();
        #pragma unroll
        for (int kk = 0; kk < 32; kk++) {
            float A0 = Ash[tm][kk], A1 = Ash[tm + 32][kk];
            #pragma unroll
            for (int r = 0; r < 13; r++) {
                float bb = Bsh[kk][dd[r]];
                acc[0][r] += A0 * bb;
                acc[1][r] += A1 * bb;
            }
        }
    }
    #pragma unroll
    for (int r = 0; r < 13; r++) {
        int d = tn + 8 * r;
        if (d < 98) {
            size_t o = ((size_t)b * 784 + h * 98 + d) * 256 + c0 + tm;
            out[o] = x[o] + acc[0][r];
            out[o + 32] = x[o + 32] + acc[1][r];
        }
    }
}

// ---------------- launch ----------------
extern "C" void kernel_launch(void* const* d_in, const int* in_sizes, int n_in,
                              void* d_out, int out_size) {
    const float* x     = (const float*)d_in[0];
    const float* wqk_w = (const float*)d_in[1];
    const float* wqk_b = (const float*)d_in[2];
    const float* wp_w  = (const float*)d_in[3];
    const float* wp_b  = (const float*)d_in[4];
    const float* wv_w  = (const float*)d_in[5];
    const float* wv_b  = (const float*)d_in[6];
    float* out = (float*)d_out;

    pool_qk_kernel<<<Bz * Ss, 256>>>(x);
    conv_kernel<<<dim3(784, 4), 256>>>(x, wv_w, wv_b);
    pool_v_kernel<<<Bz * Ss, 256>>>();
    proj_kernel<<<dim3(512, 4, 2), 256>>>(wqk_w, wqk_b, 0);
    proj_kernel<<<dim3(512, 4, 2), 256>>>(wqk_w, wqk_b, 1);
    scores_kernel<<<dim3(512, 4, 4), 256>>>();
    temp_kernel<<<512, 256>>>(wp_w, wp_b);
    softmax_kernel<<<BH * Cc, 256>>>();
    att_kernel<<<dim3(512, 4), 256>>>(x, out);
}

// round 6
// speedup vs baseline: 1.5172x; 1.5172x over previous
#include <cuda_runtime.h>
#include <cuda_bf16.h>
#include <cstdint>
#include <stdint.h>
#include <math.h>

#define Bz 64
#define Rr 28
#define Ss 784
#define Cc 256
#define Hh 8
#define DRr 98
#define Ee 128
#define BH 512

// ---------------- scratch (device globals: no runtime allocation) ----------------
__device__ float g_qpool[Bz*Ss*Cc];     // avg-pooled x, [B,S,C]
__device__ float g_kpool[Bz*Ss*Cc];     // max-pooled x, [B,S,C]
__device__ float g_vconv[Bz*Ss*Cc];     // conv out,     [B,S,C]
__device__ float g_vpool[Bz*Ss*Cc];     // pooled conv,  [B,S,C]
__device__ float g_q[BH*Cc*Ee];         // [BH,C,E]
__device__ float g_k[BH*Cc*Ee];         // [BH,C,E]
__device__ float g_scores[(size_t)BH*Cc*Cc]; // [BH,C,C] -> softmaxed in place
__device__ float g_invden[BH*Cc];       // 1/temperature per (bh,c)
// bf16 split operands for tensor-core conv
__device__ __nv_bfloat16 g_xh[Bz*Ss*Cc];
__device__ __nv_bfloat16 g_xl[Bz*Ss*Cc];
__device__ __nv_bfloat16 g_wth[Cc*2304];   // w^T hi: [cout][k=tap*256+cin]
__device__ __nv_bfloat16 g_wtl[Cc*2304];   // w^T lo

// ---------------- helpers ----------------
__device__ __forceinline__ uint32_t smem_u32(const void* p) {
    uint32_t a;
    asm("{ .reg .u64 t; cvta.to.shared.u64 t, %1; cvt.u32.u64 %0, t; }" : "=r"(a) : "l"(p));
    return a;
}
__device__ __forceinline__ void cp16(uint32_t dst, const void* src, uint32_t srcsize) {
    asm volatile("cp.async.cg.shared.global [%0], [%1], 16, %2;"
                 :: "r"(dst), "l"(src), "r"(srcsize) : "memory");
}
__device__ __forceinline__ void ldsm_x4(uint32_t* r, uint32_t addr) {
    asm volatile("ldmatrix.sync.aligned.m8n8.x4.shared.b16 {%0,%1,%2,%3}, [%4];"
                 : "=r"(r[0]), "=r"(r[1]), "=r"(r[2]), "=r"(r[3]) : "r"(addr));
}
__device__ __forceinline__ void mma16816(float* c, const uint32_t* a, const uint32_t* b) {
    asm volatile("mma.sync.aligned.m16n8k16.row.col.f32.bf16.bf16.f32 "
                 "{%0,%1,%2,%3}, {%4,%5,%6,%7}, {%8,%9}, {%0,%1,%2,%3};"
                 : "+f"(c[0]), "+f"(c[1]), "+f"(c[2]), "+f"(c[3])
                 : "r"(a[0]), "r"(a[1]), "r"(a[2]), "r"(a[3]), "r"(b[0]), "r"(b[1]));
}

// ---------------- bf16 split prep ----------------
__global__ __launch_bounds__(256) void split_x_kernel(const float* __restrict__ x) {
    int idx4 = blockIdx.x * 256 + threadIdx.x;          // 12544 blocks
    float4 v = ((const float4*)x)[idx4];
    __nv_bfloat16 h0 = __float2bfloat16(v.x), h1 = __float2bfloat16(v.y);
    __nv_bfloat16 h2 = __float2bfloat16(v.z), h3 = __float2bfloat16(v.w);
    ushort4 hp, lp;
    hp.x = __bfloat16_as_ushort(h0); hp.y = __bfloat16_as_ushort(h1);
    hp.z = __bfloat16_as_ushort(h2); hp.w = __bfloat16_as_ushort(h3);
    lp.x = __bfloat16_as_ushort(__float2bfloat16(v.x - __bfloat162float(h0)));
    lp.y = __bfloat16_as_ushort(__float2bfloat16(v.y - __bfloat162float(h1)));
    lp.z = __bfloat16_as_ushort(__float2bfloat16(v.z - __bfloat162float(h2)));
    lp.w = __bfloat16_as_ushort(__float2bfloat16(v.w - __bfloat162float(h3)));
    ((ushort4*)g_xh)[idx4] = hp;
    ((ushort4*)g_xl)[idx4] = lp;
}

__global__ __launch_bounds__(256) void split_w_kernel(const float* __restrict__ w) {
    int k = blockIdx.x;                                  // 0..2303 = tap*256+cin
    int co = threadIdx.x;
    float v = w[(size_t)k * 256 + co];
    __nv_bfloat16 h = __float2bfloat16(v);
    g_wth[(size_t)co * 2304 + k] = h;
    g_wtl[(size_t)co * 2304 + k] = __float2bfloat16(v - __bfloat162float(h));
}

// ---------------- mma.sync conv: M=50176 (128/CTA), N=256 (64/CTA), K=2304 ----------------
// stage = 64 k-elems. rows padded to 72 bf16 (144B) for conflict-free ldmatrix.
#define CROW 72
#define CA_HI 0
#define CA_LO 18432
#define CB_HI 36864
#define CB_LO 46080
#define CSTAGE 55296
#define CONV_SMEM (2*CSTAGE)

__device__ __forceinline__ void conv_load_stage(
    int s, uint32_t sb, int arow, int ahalf, int bb, int pi, int pj,
    int brow, int bq, int n0g)
{
    uint32_t bufo = sb + (uint32_t)(s & 1) * CSTAGE;
    int tap = s >> 2;
    int di = tap / 3, dj = tap - di * 3;
    int ii = pi + di - 1, jj = pj + dj - 1;
    bool valid = ((unsigned)ii < 28u) && ((unsigned)jj < 28u);
    int ci0 = ((s & 3) << 6) + ahalf * 32;
    size_t ga = ((size_t)(bb * 784 + (valid ? ii * 28 + jj : 0)) << 8) + ci0;
    uint32_t rowoff = (uint32_t)(arow * CROW + ahalf * 32) * 2;
    uint32_t vs = valid ? 16u : 0u;
    #pragma unroll
    for (int q = 0; q < 4; q++) {
        cp16(bufo + CA_HI + rowoff + q * 16, g_xh + ga + q * 8, vs);
        cp16(bufo + CA_LO + rowoff + q * 16, g_xl + ga + q * 8, vs);
    }
    // B: each thread covers 16 k-elements = 32 bytes -> TWO cp16 per hi/lo
    size_t gb = (size_t)(n0g + brow) * 2304 + (size_t)s * 64 + bq * 16;
    uint32_t boff = (uint32_t)(brow * CROW + bq * 16) * 2;
    cp16(bufo + CB_HI + boff,      g_wth + gb,     16u);
    cp16(bufo + CB_HI + boff + 16, g_wth + gb + 8, 16u);
    cp16(bufo + CB_LO + boff,      g_wtl + gb,     16u);
    cp16(bufo + CB_LO + boff + 16, g_wtl + gb + 8, 16u);
    asm volatile("cp.async.commit_group;" ::: "memory");
}

__global__ __launch_bounds__(256) void conv_mma_kernel(const float* __restrict__ bias) {
    extern __shared__ char smem[];
    uint32_t sb = smem_u32(smem);
    int t = threadIdx.x, lane = t & 31, wid = t >> 5;
    int warp_m = wid >> 1, warp_n = wid & 1;
    int m0 = blockIdx.x << 7;
    int n0g = blockIdx.y << 6;

    // A loader geometry: 2 threads per output row
    int arow = t >> 1, ahalf = t & 1;
    int m = m0 + arow;
    int bb = m / 784;
    int pix = m - bb * 784;
    int pi = pix / 28, pj = pix - pi * 28;
    // B loader geometry: 4 threads per cout row (16 k-elems each)
    int brow = t >> 2, bq = t & 3;

    float c[2][4][4];
    #pragma unroll
    for (int mb = 0; mb < 2; mb++)
        #pragma unroll
        for (int nb = 0; nb < 4; nb++)
            #pragma unroll
            for (int r = 0; r < 4; r++) c[mb][nb][r] = 0.f;

    // ldmatrix lane addressing
    int a_r = lane & 15;
    int a_c = (lane >> 4) << 3;
    int b_r = (lane & 7) | ((lane & 16) >> 1);
    int b_c = lane & 8;

    conv_load_stage(0, sb, arow, ahalf, bb, pi, pj, brow, bq, n0g);

    for (int s = 0; s < 36; s++) {
        if (s + 1 < 36) {
            conv_load_stage(s + 1, sb, arow, ahalf, bb, pi, pj, brow, bq, n0g);
            asm volatile("cp.async.wait_group 1;" ::: "memory");
        } else {
            asm volatile("cp.async.wait_group 0;" ::: "memory");
        }
        __syncthreads();

        uint32_t bufo = sb + (uint32_t)(s & 1) * CSTAGE;
        #pragma unroll
        for (int kk = 0; kk < 4; kk++) {
            int k0 = kk << 4;
            uint32_t a_hi[2][4], a_lo[2][4];
            #pragma unroll
            for (int mb = 0; mb < 2; mb++) {
                uint32_t off = (uint32_t)((warp_m * 32 + mb * 16 + a_r) * CROW + k0 + a_c) * 2;
                ldsm_x4(a_hi[mb], bufo + CA_HI + off);
                ldsm_x4(a_lo[mb], bufo + CA_LO + off);
            }
            uint32_t b_hi[4][2], b_lo[4][2];
            #pragma unroll
            for (int nb2 = 0; nb2 < 2; nb2++) {
                uint32_t off = (uint32_t)((warp_n * 32 + nb2 * 16 + b_r) * CROW + k0 + b_c) * 2;
                uint32_t r4[4];
                ldsm_x4(r4, bufo + CB_HI + off);
                b_hi[nb2*2][0] = r4[0]; b_hi[nb2*2][1] = r4[1];
                b_hi[nb2*2+1][0] = r4[2]; b_hi[nb2*2+1][1] = r4[3];
                ldsm_x4(r4, bufo + CB_LO + off);
                b_lo[nb2*2][0] = r4[0]; b_lo[nb2*2][1] = r4[1];
                b_lo[nb2*2+1][0] = r4[2]; b_lo[nb2*2+1][1] = r4[3];
            }
            #pragma unroll
            for (int mb = 0; mb < 2; mb++)
                #pragma unroll
                for (int nb = 0; nb < 4; nb++) {
                    mma16816(c[mb][nb], a_hi[mb], b_hi[nb]);
                    mma16816(c[mb][nb], a_hi[mb], b_lo[nb]);
                    mma16816(c[mb][nb], a_lo[mb], b_hi[nb]);
                }
        }
        __syncthreads();
    }

    // epilogue: bias add + store
    #pragma unroll
    for (int mb = 0; mb < 2; mb++) {
        int rg = m0 + warp_m * 32 + mb * 16 + (lane >> 2);
        #pragma unroll
        for (int nb = 0; nb < 4; nb++) {
            int cg = n0g + warp_n * 32 + nb * 8 + ((lane & 3) << 1);
            float2 bz = *(const float2*)(bias + cg);
            *(float2*)(g_vconv + (size_t)rg * 256 + cg) =
                make_float2(c[mb][nb][0] + bz.x, c[mb][nb][1] + bz.y);
            *(float2*)(g_vconv + (size_t)(rg + 8) * 256 + cg) =
                make_float2(c[mb][nb][2] + bz.x, c[mb][nb][3] + bz.y);
        }
    }
}

// ---------------- pooling: avg (valid-count) + max, SAME ----------------
__global__ __launch_bounds__(256) void pool_qk_kernel(const float* __restrict__ x) {
    int bs = blockIdx.x;
    int c  = threadIdx.x;
    int b  = bs / 784;
    int pix = bs - b * 784;
    int i = pix / 28, j = pix - i * 28;
    const float* xb = x + (size_t)b * 784 * 256;
    float sum = 0.f, mx = -INFINITY;
    int cnt = 0;
    #pragma unroll
    for (int di = -1; di <= 1; di++) {
        #pragma unroll
        for (int dj = -1; dj <= 1; dj++) {
            int ii = i + di, jj = j + dj;
            if ((unsigned)ii < 28u && (unsigned)jj < 28u) {
                float v = xb[(size_t)(ii * 28 + jj) * 256 + c];
                sum += v;
                mx = fmaxf(mx, v);
                cnt++;
            }
        }
    }
    size_t o = (size_t)bs * 256 + c;
    g_qpool[o] = sum / (float)cnt;
    g_kpool[o] = mx;
}

__global__ __launch_bounds__(256) void pool_v_kernel() {
    int bs = blockIdx.x;
    int c  = threadIdx.x;
    int b  = bs / 784;
    int pix = bs - b * 784;
    int i = pix / 28, j = pix - i * 28;
    const float* xb = g_vconv + (size_t)b * 784 * 256;
    float sum = 0.f;
    int cnt = 0;
    #pragma unroll
    for (int di = -1; di <= 1; di++) {
        #pragma unroll
        for (int dj = -1; dj <= 1; dj++) {
            int ii = i + di, jj = j + dj;
            if ((unsigned)ii < 28u && (unsigned)jj < 28u) {
                sum += xb[(size_t)(ii * 28 + jj) * 256 + c];
                cnt++;
            }
        }
    }
    g_vpool[(size_t)bs * 256 + c] = sum / (float)cnt;
}

// ---------------- q/k projection: per (b,h) GEMM [256c x 98d] @ [98d x 128e] ----------------
__global__ __launch_bounds__(256) void proj_kernel(const float* __restrict__ wqk,
                                                   const float* __restrict__ bias,
                                                   int which) {
    __shared__ float As[16][68];
    __shared__ float Bs[16][68];
    const float* pool = which ? g_kpool : g_qpool;
    float* out = which ? g_k : g_q;
    int t = threadIdx.x;
    int bh = blockIdx.x;
    int b = bh >> 3, h = bh & 7;
    int c0 = blockIdx.y << 6, e0 = blockIdx.z << 6;
    const float* pbase = pool + ((size_t)b * 784 + h * 98) * 256;
    const float* wbase = wqk + (size_t)h * 98 * 128;
    int ld = t >> 4, lc = (t & 15) << 2;
    int ty = t >> 4, tx = t & 15;
    float acc[4][4];
    #pragma unroll
    for (int a_ = 0; a_ < 4; a_++)
        #pragma unroll
        for (int b_ = 0; b_ < 4; b_++) acc[a_][b_] = 0.f;

    for (int kc = 0; kc < 7; kc++) {
        int d = kc * 16 + ld;
        float4 av = make_float4(0.f, 0.f, 0.f, 0.f);
        float4 bv = make_float4(0.f, 0.f, 0.f, 0.f);
        if (d < 98) {
            av = *(const float4*)(pbase + (size_t)d * 256 + c0 + lc);
            bv = *(const float4*)(wbase + (size_t)d * 128 + e0 + lc);
        }
        __syncthreads();
        *(float4*)&As[ld][lc] = av;
        *(float4*)&Bs[ld][lc] = bv;
        __syncthreads();
        #pragma unroll
        for (int kk = 0; kk < 16; kk++) {
            float4 a  = *(const float4*)&As[kk][ty << 2];
            float4 b4 = *(const float4*)&Bs[kk][tx << 2];
            float ar[4] = {a.x, a.y, a.z, a.w};
            float br[4] = {b4.x, b4.y, b4.z, b4.w};
            #pragma unroll
            for (int i_ = 0; i_ < 4; i_++)
                #pragma unroll
                for (int j_ = 0; j_ < 4; j_++) acc[i_][j_] += ar[i_] * br[j_];
        }
    }
    float4 bz = *(const float4*)(bias + h * 128 + e0 + (tx << 2));
    #pragma unroll
    for (int i_ = 0; i_ < 4; i_++) {
        int c = c0 + (ty << 2) + i_;
        float4 r = make_float4(acc[i_][0] + bz.x, acc[i_][1] + bz.y,
                               acc[i_][2] + bz.z, acc[i_][3] + bz.w);
        *(float4*)(out + ((size_t)bh * 256 + c) * 128 + e0 + (tx << 2)) = r;
    }
}

// ---------------- scores: per (b,h) q[256,128] @ k[256,128]^T ----------------
__global__ __launch_bounds__(256) void scores_kernel() {
    __shared__ float As[16][68];
    __shared__ float Bs[16][68];
    int t = threadIdx.x;
    int bh = blockIdx.x;
    int c0 = blockIdx.y << 6, f0 = blockIdx.z << 6;
    const float* qb = g_q + (size_t)bh * Cc * Ee;
    const float* kb = g_k + (size_t)bh * Cc * Ee;
    int lr = t >> 2, lq = t & 3;
    int ty = t >> 4, tx = t & 15;
    float acc[4][4];
    #pragma unroll
    for (int a_ = 0; a_ < 4; a_++)
        #pragma unroll
        for (int b_ = 0; b_ < 4; b_++) acc[a_][b_] = 0.f;

    for (int kc = 0; kc < 8; kc++) {
        int e4 = kc * 16 + (lq << 2);
        float4 av = *(const float4*)(qb + (size_t)(c0 + lr) * 128 + e4);
        float4 bv = *(const float4*)(kb + (size_t)(f0 + lr) * 128 + e4);
        __syncthreads();
        As[(lq << 2) + 0][lr] = av.x;
        As[(lq << 2) + 1][lr] = av.y;
        As[(lq << 2) + 2][lr] = av.z;
        As[(lq << 2) + 3][lr] = av.w;
        Bs[(lq << 2) + 0][lr] = bv.x;
        Bs[(lq << 2) + 1][lr] = bv.y;
        Bs[(lq << 2) + 2][lr] = bv.z;
        Bs[(lq << 2) + 3][lr] = bv.w;
        __syncthreads();
        #pragma unroll
        for (int kk = 0; kk < 16; kk++) {
            float4 a  = *(const float4*)&As[kk][ty << 2];
            float4 b4 = *(const float4*)&Bs[kk][tx << 2];
            float ar[4] = {a.x, a.y, a.z, a.w};
            float br[4] = {b4.x, b4.y, b4.z, b4.w};
            #pragma unroll
            for (int i_ = 0; i_ < 4; i_++)
                #pragma unroll
                for (int j_ = 0; j_ < 4; j_++) acc[i_][j_] += ar[i_] * br[j_];
        }
    }
    #pragma unroll
    for (int i_ = 0; i_ < 4; i_++) {
        size_t row = (size_t)bh * 256 + c0 + (ty << 2) + i_;
        *(float4*)(g_scores + row * 256 + f0 + (tx << 2)) =
            make_float4(acc[i_][0], acc[i_][1], acc[i_][2], acc[i_][3]);
    }
}

// ---------------- temperature ----------------
__global__ __launch_bounds__(256) void temp_kernel(const float* __restrict__ wp_w,
                                                   const float* __restrict__ wp_b) {
    __shared__ float kbar[128];
    __shared__ float rowmean[256];
    int bh = blockIdx.x;
    int t = threadIdx.x;
    const float* kb = g_k + (size_t)bh * Cc * Ee;
    const float* qb = g_q + (size_t)bh * Cc * Ee;
    if (t < 128) {
        float s = 0.f;
        for (int f = 0; f < 256; f++) s += kb[(size_t)f * 128 + t];
        kbar[t] = s * (1.f / 256.f);
    }
    __syncthreads();
    int w = t >> 5, lane = t & 31;
    float4 kv = *(const float4*)&kbar[lane << 2];
    for (int r = 0; r < 32; r++) {
        int c = (w << 5) + r;
        float4 qv = *(const float4*)(qb + (size_t)c * 128 + (lane << 2));
        float p = qv.x * kv.x + qv.y * kv.y + qv.z * kv.z + qv.w * kv.w;
        #pragma unroll
        for (int o = 16; o; o >>= 1) p += __shfl_xor_sync(0xFFFFFFFFu, p, o);
        if (lane == 0) rowmean[c] = p;
    }
    __syncthreads();
    float s = wp_b[t];
    for (int cc = 0; cc < 256; cc++) s += rowmean[cc] * wp_w[(size_t)cc * 256 + t];
    float sig = 1.f / (1.f + expf(-s));
    g_invden[(size_t)bh * 256 + t] = exp2f(-7.f * (0.2f + sig));
}

// ---------------- softmax ----------------
__global__ __launch_bounds__(256) void softmax_kernel() {
    __shared__ float red[8];
    int row = blockIdx.x;
    int t = threadIdx.x;
    float invd = g_invden[row];
    float* sp = g_scores + (size_t)row * 256;
    float v = sp[t] * invd;
    float m = v;
    #pragma unroll
    for (int o = 16; o; o >>= 1) m = fmaxf(m, __shfl_xor_sync(0xFFFFFFFFu, m, o));
    if ((t & 31) == 0) red[t >> 5] = m;
    __syncthreads();
    float bm = red[0];
    #pragma unroll
    for (int i = 1; i < 8; i++) bm = fmaxf(bm, red[i]);
    float e = expf(v - bm);
    __syncthreads();
    float s = e;
    #pragma unroll
    for (int o = 16; o; o >>= 1) s += __shfl_xor_sync(0xFFFFFFFFu, s, o);
    if ((t & 31) == 0) red[t >> 5] = s;
    __syncthreads();
    float tot = 0.f;
    #pragma unroll
    for (int i = 0; i < 8; i++) tot += red[i];
    sp[t] = e / tot;
}

// ---------------- att = weights @ v + residual ----------------
__global__ __launch_bounds__(256) void att_kernel(const float* __restrict__ x,
                                                  float* __restrict__ out) {
    __shared__ float Ash[64][33];
    __shared__ float Bsh[32][99];
    int t = threadIdx.x;
    int bh = blockIdx.x;
    int b = bh >> 3, h = bh & 7;
    int c0 = blockIdx.y << 6;
    const float* wrow = g_scores + ((size_t)bh * 256 + c0) * 256;
    const float* vb = g_vpool + ((size_t)b * 784 + h * 98) * 256;
    int tm = t & 31, tn = t >> 5;
    int dd[13];
    #pragma unroll
    for (int r = 0; r < 13; r++) {
        int d = tn + 8 * r;
        dd[r] = (d < 98) ? d : 0;
    }
    float acc[2][13];
    #pragma unroll
    for (int a_ = 0; a_ < 2; a_++)
        #pragma unroll
        for (int r = 0; r < 13; r++) acc[a_][r] = 0.f;

    int ar0 = t >> 3, aq0 = t & 7;
    for (int kc = 0; kc < 8; kc++) {
        int k0 = kc << 5;
        float4 av0 = *(const float4*)(wrow + (size_t)ar0 * 256 + k0 + (aq0 << 2));
        float4 av1 = *(const float4*)(wrow + (size_t)(ar0 + 32) * 256 + k0 + (aq0 << 2));
        float bstage[13];
        #pragma unroll
        for (int it = 0; it < 13; it++) {
            int idx = t + (it << 8);
            if (idx < 3136) {
                int kk = idx & 31, d = idx >> 5;
                bstage[it] = vb[(size_t)d * 256 + k0 + kk];
            }
        }
        __syncthreads();
        Ash[ar0][(aq0 << 2) + 0] = av0.x;
        Ash[ar0][(aq0 << 2) + 1] = av0.y;
        Ash[ar0][(aq0 << 2) + 2] = av0.z;
        Ash[ar0][(aq0 << 2) + 3] = av0.w;
        Ash[ar0 + 32][(aq0 << 2) + 0] = av1.x;
        Ash[ar0 + 32][(aq0 << 2) + 1] = av1.y;
        Ash[ar0 + 32][(aq0 << 2) + 2] = av1.z;
        Ash[ar0 + 32][(aq0 << 2) + 3] = av1.w;
        #pragma unroll
        for (int it = 0; it < 13; it++) {
            int idx = t + (it << 8);
            if (idx < 3136) Bsh[idx & 31][idx >> 5] = bstage[it];
        }
        __syncthreads();
        #pragma unroll
        for (int kk = 0; kk < 32; kk++) {
            float A0 = Ash[tm][kk], A1 = Ash[tm + 32][kk];
            #pragma unroll
            for (int r = 0; r < 13; r++) {
                float bb = Bsh[kk][dd[r]];
                acc[0][r] += A0 * bb;
                acc[1][r] += A1 * bb;
            }
        }
    }
    #pragma unroll
    for (int r = 0; r < 13; r++) {
        int d = tn + 8 * r;
        if (d < 98) {
            size_t o = ((size_t)b * 784 + h * 98 + d) * 256 + c0 + tm;
            out[o] = x[o] + acc[0][r];
            out[o + 32] = x[o + 32] + acc[1][r];
        }
    }
}

// ---------------- launch ----------------
extern "C" void kernel_launch(void* const* d_in, const int* in_sizes, int n_in,
                              void* d_out, int out_size) {
    const float* x     = (const float*)d_in[0];
    const float* wqk_w = (const float*)d_in[1];
    const float* wqk_b = (const float*)d_in[2];
    const float* wp_w  = (const float*)d_in[3];
    const float* wp_b  = (const float*)d_in[4];
    const float* wv_w  = (const float*)d_in[5];
    const float* wv_b  = (const float*)d_in[6];
    float* out = (float*)d_out;

    cudaFuncSetAttribute(conv_mma_kernel, cudaFuncAttributeMaxDynamicSharedMemorySize, CONV_SMEM);

    split_x_kernel<<<12544, 256>>>(x);
    split_w_kernel<<<2304, 256>>>(wv_w);
    conv_mma_kernel<<<dim3(392, 4), 256, CONV_SMEM>>>(wv_b);
    pool_qk_kernel<<<Bz * Ss, 256>>>(x);
    pool_v_kernel<<<Bz * Ss, 256>>>();
    proj_kernel<<<dim3(512, 4, 2), 256>>>(wqk_w, wqk_b, 0);
    proj_kernel<<<dim3(512, 4, 2), 256>>>(wqk_w, wqk_b, 1);
    scores_kernel<<<dim3(512, 4, 4), 256>>>();
    temp_kernel<<<512, 256>>>(wp_w, wp_b);
    softmax_kernel<<<BH * Cc, 256>>>();
    att_kernel<<<dim3(512, 4), 256>>>(x, out);
}

// round 7
// speedup vs baseline: 1.7312x; 1.1410x over previous
#include <cuda_runtime.h>
#include <cuda_bf16.h>
#include <cstdint>
#include <stdint.h>
#include <math.h>

#define Bz 64
#define Rr 28
#define Ss 784
#define Cc 256
#define Hh 8
#define DRr 98
#define Ee 128
#define BH 512

// ---------------- scratch (device globals: no runtime allocation) ----------------
__device__ float g_qpool[Bz*Ss*Cc];     // avg-pooled x, [B,S,C]
__device__ float g_kpool[Bz*Ss*Cc];     // max-pooled x, [B,S,C]
__device__ float g_vconv[Bz*Ss*Cc];     // conv out,     [B,S,C]
__device__ float g_vpool[Bz*Ss*Cc];     // pooled conv,  [B,S,C]
__device__ float g_q[BH*Cc*Ee];         // [BH,C,E] fp32 (temp kernel)
__device__ float g_k[BH*Cc*Ee];
__device__ float g_scores[(size_t)BH*Cc*Cc]; // [BH,C,C] -> holds normalized weights
__device__ float g_invden[BH*Cc];       // 1/temperature per (bh,c)
// bf16 split operands for tensor-core conv
__device__ __nv_bfloat16 g_xh[Bz*Ss*Cc];
__device__ __nv_bfloat16 g_xl[Bz*Ss*Cc];
__device__ __nv_bfloat16 g_wth[Cc*2304];   // w^T hi: [cout][k=tap*256+cin]
__device__ __nv_bfloat16 g_wtl[Cc*2304];   // w^T lo
// bf16 splits of q/k for tensor-core scores
__device__ __nv_bfloat16 g_qsh[BH*Cc*Ee];
__device__ __nv_bfloat16 g_qsl[BH*Cc*Ee];
__device__ __nv_bfloat16 g_ksh[BH*Cc*Ee];
__device__ __nv_bfloat16 g_ksl[BH*Cc*Ee];

// ---------------- helpers ----------------
__device__ __forceinline__ uint32_t smem_u32(const void* p) {
    uint32_t a;
    asm("{ .reg .u64 t; cvta.to.shared.u64 t, %1; cvt.u32.u64 %0, t; }" : "=r"(a) : "l"(p));
    return a;
}
__device__ __forceinline__ void cp16(uint32_t dst, const void* src, uint32_t srcsize) {
    asm volatile("cp.async.cg.shared.global [%0], [%1], 16, %2;"
                 :: "r"(dst), "l"(src), "r"(srcsize) : "memory");
}
__device__ __forceinline__ void ldsm_x4(uint32_t* r, uint32_t addr) {
    asm volatile("ldmatrix.sync.aligned.m8n8.x4.shared.b16 {%0,%1,%2,%3}, [%4];"
                 : "=r"(r[0]), "=r"(r[1]), "=r"(r[2]), "=r"(r[3]) : "r"(addr));
}
__device__ __forceinline__ void mma16816(float* c, const uint32_t* a, const uint32_t* b) {
    asm volatile("mma.sync.aligned.m16n8k16.row.col.f32.bf16.bf16.f32 "
                 "{%0,%1,%2,%3}, {%4,%5,%6,%7}, {%8,%9}, {%0,%1,%2,%3};"
                 : "+f"(c[0]), "+f"(c[1]), "+f"(c[2]), "+f"(c[3])
                 : "r"(a[0]), "r"(a[1]), "r"(a[2]), "r"(a[3]), "r"(b[0]), "r"(b[1]));
}
__device__ __forceinline__ void split2(float v, __nv_bfloat16& h, __nv_bfloat16& l) {
    h = __float2bfloat16(v);
    l = __float2bfloat16(v - __bfloat162float(h));
}

// ---------------- bf16 split prep ----------------
__global__ __launch_bounds__(256) void split_x_kernel(const float* __restrict__ x) {
    int idx4 = blockIdx.x * 256 + threadIdx.x;
    float4 v = ((const float4*)x)[idx4];
    __nv_bfloat16 h0, h1, h2, h3, l0, l1, l2, l3;
    split2(v.x, h0, l0); split2(v.y, h1, l1);
    split2(v.z, h2, l2); split2(v.w, h3, l3);
    ushort4 hp, lp;
    hp.x = __bfloat16_as_ushort(h0); hp.y = __bfloat16_as_ushort(h1);
    hp.z = __bfloat16_as_ushort(h2); hp.w = __bfloat16_as_ushort(h3);
    lp.x = __bfloat16_as_ushort(l0); lp.y = __bfloat16_as_ushort(l1);
    lp.z = __bfloat16_as_ushort(l2); lp.w = __bfloat16_as_ushort(l3);
    ((ushort4*)g_xh)[idx4] = hp;
    ((ushort4*)g_xl)[idx4] = lp;
}

__global__ __launch_bounds__(256) void split_w_kernel(const float* __restrict__ w) {
    int k = blockIdx.x;
    int co = threadIdx.x;
    float v = w[(size_t)k * 256 + co];
    __nv_bfloat16 h, l;
    split2(v, h, l);
    g_wth[(size_t)co * 2304 + k] = h;
    g_wtl[(size_t)co * 2304 + k] = l;
}

// ---------------- mma.sync conv: M=50176 (128/CTA), N=256 (64/CTA), K=2304 ----------------
#define CROW 72
#define CA_HI 0
#define CA_LO 18432
#define CB_HI 36864
#define CB_LO 46080
#define CSTAGE 55296
#define CONV_SMEM (2*CSTAGE)

__device__ __forceinline__ void conv_load_stage(
    int s, uint32_t sb, int arow, int ahalf, int bb, int pi, int pj,
    int brow, int bq, int n0g)
{
    uint32_t bufo = sb + (uint32_t)(s & 1) * CSTAGE;
    int tap = s >> 2;
    int di = tap / 3, dj = tap - di * 3;
    int ii = pi + di - 1, jj = pj + dj - 1;
    bool valid = ((unsigned)ii < 28u) && ((unsigned)jj < 28u);
    int ci0 = ((s & 3) << 6) + ahalf * 32;
    size_t ga = ((size_t)(bb * 784 + (valid ? ii * 28 + jj : 0)) << 8) + ci0;
    uint32_t rowoff = (uint32_t)(arow * CROW + ahalf * 32) * 2;
    uint32_t vs = valid ? 16u : 0u;
    #pragma unroll
    for (int q = 0; q < 4; q++) {
        cp16(bufo + CA_HI + rowoff + q * 16, g_xh + ga + q * 8, vs);
        cp16(bufo + CA_LO + rowoff + q * 16, g_xl + ga + q * 8, vs);
    }
    size_t gb = (size_t)(n0g + brow) * 2304 + (size_t)s * 64 + bq * 16;
    uint32_t boff = (uint32_t)(brow * CROW + bq * 16) * 2;
    cp16(bufo + CB_HI + boff,      g_wth + gb,     16u);
    cp16(bufo + CB_HI + boff + 16, g_wth + gb + 8, 16u);
    cp16(bufo + CB_LO + boff,      g_wtl + gb,     16u);
    cp16(bufo + CB_LO + boff + 16, g_wtl + gb + 8, 16u);
    asm volatile("cp.async.commit_group;" ::: "memory");
}

__global__ __launch_bounds__(256) void conv_mma_kernel(const float* __restrict__ bias) {
    extern __shared__ char smem[];
    uint32_t sb = smem_u32(smem);
    int t = threadIdx.x, lane = t & 31, wid = t >> 5;
    int warp_m = wid >> 1, warp_n = wid & 1;
    int m0 = blockIdx.x << 7;
    int n0g = blockIdx.y << 6;

    int arow = t >> 1, ahalf = t & 1;
    int m = m0 + arow;
    int bb = m / 784;
    int pix = m - bb * 784;
    int pi = pix / 28, pj = pix - pi * 28;
    int brow = t >> 2, bq = t & 3;

    float c[2][4][4];
    #pragma unroll
    for (int mb = 0; mb < 2; mb++)
        #pragma unroll
        for (int nb = 0; nb < 4; nb++)
            #pragma unroll
            for (int r = 0; r < 4; r++) c[mb][nb][r] = 0.f;

    int a_r = lane & 15;
    int a_c = (lane >> 4) << 3;
    int b_r = (lane & 7) | ((lane & 16) >> 1);
    int b_c = lane & 8;

    conv_load_stage(0, sb, arow, ahalf, bb, pi, pj, brow, bq, n0g);

    for (int s = 0; s < 36; s++) {
        if (s + 1 < 36) {
            conv_load_stage(s + 1, sb, arow, ahalf, bb, pi, pj, brow, bq, n0g);
            asm volatile("cp.async.wait_group 1;" ::: "memory");
        } else {
            asm volatile("cp.async.wait_group 0;" ::: "memory");
        }
        __syncthreads();

        uint32_t bufo = sb + (uint32_t)(s & 1) * CSTAGE;
        #pragma unroll
        for (int kk = 0; kk < 4; kk++) {
            int k0 = kk << 4;
            uint32_t a_hi[2][4], a_lo[2][4];
            #pragma unroll
            for (int mb = 0; mb < 2; mb++) {
                uint32_t off = (uint32_t)((warp_m * 32 + mb * 16 + a_r) * CROW + k0 + a_c) * 2;
                ldsm_x4(a_hi[mb], bufo + CA_HI + off);
                ldsm_x4(a_lo[mb], bufo + CA_LO + off);
            }
            uint32_t b_hi[4][2], b_lo[4][2];
            #pragma unroll
            for (int nb2 = 0; nb2 < 2; nb2++) {
                uint32_t off = (uint32_t)((warp_n * 32 + nb2 * 16 + b_r) * CROW + k0 + b_c) * 2;
                uint32_t r4[4];
                ldsm_x4(r4, bufo + CB_HI + off);
                b_hi[nb2*2][0] = r4[0]; b_hi[nb2*2][1] = r4[1];
                b_hi[nb2*2+1][0] = r4[2]; b_hi[nb2*2+1][1] = r4[3];
                ldsm_x4(r4, bufo + CB_LO + off);
                b_lo[nb2*2][0] = r4[0]; b_lo[nb2*2][1] = r4[1];
                b_lo[nb2*2+1][0] = r4[2]; b_lo[nb2*2+1][1] = r4[3];
            }
            #pragma unroll
            for (int mb = 0; mb < 2; mb++)
                #pragma unroll
                for (int nb = 0; nb < 4; nb++) {
                    mma16816(c[mb][nb], a_hi[mb], b_hi[nb]);
                    mma16816(c[mb][nb], a_hi[mb], b_lo[nb]);
                    mma16816(c[mb][nb], a_lo[mb], b_hi[nb]);
                }
        }
        __syncthreads();
    }

    #pragma unroll
    for (int mb = 0; mb < 2; mb++) {
        int rg = m0 + warp_m * 32 + mb * 16 + (lane >> 2);
        #pragma unroll
        for (int nb = 0; nb < 4; nb++) {
            int cg = n0g + warp_n * 32 + nb * 8 + ((lane & 3) << 1);
            float2 bz = *(const float2*)(bias + cg);
            *(float2*)(g_vconv + (size_t)rg * 256 + cg) =
                make_float2(c[mb][nb][0] + bz.x, c[mb][nb][1] + bz.y);
            *(float2*)(g_vconv + (size_t)(rg + 8) * 256 + cg) =
                make_float2(c[mb][nb][2] + bz.x, c[mb][nb][3] + bz.y);
        }
    }
}

// ---------------- pooling: avg (valid-count) + max, SAME ----------------
__global__ __launch_bounds__(256) void pool_qk_kernel(const float* __restrict__ x) {
    int bs = blockIdx.x;
    int c  = threadIdx.x;
    int b  = bs / 784;
    int pix = bs - b * 784;
    int i = pix / 28, j = pix - i * 28;
    const float* xb = x + (size_t)b * 784 * 256;
    float sum = 0.f, mx = -INFINITY;
    int cnt = 0;
    #pragma unroll
    for (int di = -1; di <= 1; di++) {
        #pragma unroll
        for (int dj = -1; dj <= 1; dj++) {
            int ii = i + di, jj = j + dj;
            if ((unsigned)ii < 28u && (unsigned)jj < 28u) {
                float v = xb[(size_t)(ii * 28 + jj) * 256 + c];
                sum += v;
                mx = fmaxf(mx, v);
                cnt++;
            }
        }
    }
    size_t o = (size_t)bs * 256 + c;
    g_qpool[o] = sum / (float)cnt;
    g_kpool[o] = mx;
}

__global__ __launch_bounds__(256) void pool_v_kernel() {
    int bs = blockIdx.x;
    int c  = threadIdx.x;
    int b  = bs / 784;
    int pix = bs - b * 784;
    int i = pix / 28, j = pix - i * 28;
    const float* xb = g_vconv + (size_t)b * 784 * 256;
    float sum = 0.f;
    int cnt = 0;
    #pragma unroll
    for (int di = -1; di <= 1; di++) {
        #pragma unroll
        for (int dj = -1; dj <= 1; dj++) {
            int ii = i + di, jj = j + dj;
            if ((unsigned)ii < 28u && (unsigned)jj < 28u) {
                sum += xb[(size_t)(ii * 28 + jj) * 256 + c];
                cnt++;
            }
        }
    }
    g_vpool[(size_t)bs * 256 + c] = sum / (float)cnt;
}

// ---------------- q/k projection: fp32 out + bf16 split out ----------------
__global__ __launch_bounds__(256) void proj_kernel(const float* __restrict__ wqk,
                                                   const float* __restrict__ bias,
                                                   int which) {
    __shared__ float As[16][68];
    __shared__ float Bs[16][68];
    const float* pool = which ? g_kpool : g_qpool;
    float* out = which ? g_k : g_q;
    __nv_bfloat16* outh = which ? g_ksh : g_qsh;
    __nv_bfloat16* outl = which ? g_ksl : g_qsl;
    int t = threadIdx.x;
    int bh = blockIdx.x;
    int b = bh >> 3, h = bh & 7;
    int c0 = blockIdx.y << 6, e0 = blockIdx.z << 6;
    const float* pbase = pool + ((size_t)b * 784 + h * 98) * 256;
    const float* wbase = wqk + (size_t)h * 98 * 128;
    int ld = t >> 4, lc = (t & 15) << 2;
    int ty = t >> 4, tx = t & 15;
    float acc[4][4];
    #pragma unroll
    for (int a_ = 0; a_ < 4; a_++)
        #pragma unroll
        for (int b_ = 0; b_ < 4; b_++) acc[a_][b_] = 0.f;

    for (int kc = 0; kc < 7; kc++) {
        int d = kc * 16 + ld;
        float4 av = make_float4(0.f, 0.f, 0.f, 0.f);
        float4 bv = make_float4(0.f, 0.f, 0.f, 0.f);
        if (d < 98) {
            av = *(const float4*)(pbase + (size_t)d * 256 + c0 + lc);
            bv = *(const float4*)(wbase + (size_t)d * 128 + e0 + lc);
        }
        __syncthreads();
        *(float4*)&As[ld][lc] = av;
        *(float4*)&Bs[ld][lc] = bv;
        __syncthreads();
        #pragma unroll
        for (int kk = 0; kk < 16; kk++) {
            float4 a  = *(const float4*)&As[kk][ty << 2];
            float4 b4 = *(const float4*)&Bs[kk][tx << 2];
            float ar[4] = {a.x, a.y, a.z, a.w};
            float br[4] = {b4.x, b4.y, b4.z, b4.w};
            #pragma unroll
            for (int i_ = 0; i_ < 4; i_++)
                #pragma unroll
                for (int j_ = 0; j_ < 4; j_++) acc[i_][j_] += ar[i_] * br[j_];
        }
    }
    float4 bz = *(const float4*)(bias + h * 128 + e0 + (tx << 2));
    #pragma unroll
    for (int i_ = 0; i_ < 4; i_++) {
        int c = c0 + (ty << 2) + i_;
        float4 r = make_float4(acc[i_][0] + bz.x, acc[i_][1] + bz.y,
                               acc[i_][2] + bz.z, acc[i_][3] + bz.w);
        size_t oidx = ((size_t)bh * 256 + c) * 128 + e0 + (tx << 2);
        *(float4*)(out + oidx) = r;
        __nv_bfloat16 h0, h1, h2, h3, l0, l1, l2, l3;
        split2(r.x, h0, l0); split2(r.y, h1, l1);
        split2(r.z, h2, l2); split2(r.w, h3, l3);
        ushort4 hp, lp;
        hp.x = __bfloat16_as_ushort(h0); hp.y = __bfloat16_as_ushort(h1);
        hp.z = __bfloat16_as_ushort(h2); hp.w = __bfloat16_as_ushort(h3);
        lp.x = __bfloat16_as_ushort(l0); lp.y = __bfloat16_as_ushort(l1);
        lp.z = __bfloat16_as_ushort(l2); lp.w = __bfloat16_as_ushort(l3);
        *(ushort4*)(outh + oidx) = hp;
        *(ushort4*)(outl + oidx) = lp;
    }
}

// ---------------- temperature ----------------
__global__ __launch_bounds__(256) void temp_kernel(const float* __restrict__ wp_w,
                                                   const float* __restrict__ wp_b) {
    __shared__ float kbar[128];
    __shared__ float rowmean[256];
    int bh = blockIdx.x;
    int t = threadIdx.x;
    const float* kb = g_k + (size_t)bh * Cc * Ee;
    const float* qb = g_q + (size_t)bh * Cc * Ee;
    if (t < 128) {
        float s = 0.f;
        for (int f = 0; f < 256; f++) s += kb[(size_t)f * 128 + t];
        kbar[t] = s * (1.f / 256.f);
    }
    __syncthreads();
    int w = t >> 5, lane = t & 31;
    float4 kv = *(const float4*)&kbar[lane << 2];
    for (int r = 0; r < 32; r++) {
        int c = (w << 5) + r;
        float4 qv = *(const float4*)(qb + (size_t)c * 128 + (lane << 2));
        float p = qv.x * kv.x + qv.y * kv.y + qv.z * kv.z + qv.w * kv.w;
        #pragma unroll
        for (int o = 16; o; o >>= 1) p += __shfl_xor_sync(0xFFFFFFFFu, p, o);
        if (lane == 0) rowmean[c] = p;
    }
    __syncthreads();
    float s = wp_b[t];
    for (int cc = 0; cc < 256; cc++) s += rowmean[cc] * wp_w[(size_t)cc * 256 + t];
    float sig = 1.f / (1.f + expf(-s));
    g_invden[(size_t)bh * 256 + t] = exp2f(-7.f * (0.2f + sig));
}

// ---------------- fused scores (HMMA, error-split) + temperature scale + softmax ----------------
// per CTA: bh, 64-row c-tile. q tile 64x128 in smem, k full 256x128 in smem.
#define SROW 136
#define SQ_HI 0
#define SQ_LO 17408
#define SK_HI 34816
#define SK_LO 104448
#define SRED  174080
#define SS_SMEM 176128

__global__ __launch_bounds__(256) void scores_softmax_kernel() {
    extern __shared__ char smem[];
    uint32_t sb = smem_u32(smem);
    float* red = (float*)(smem + SRED);           // [64][8]: cols 0..3 max, 4..7 sum
    int t = threadIdx.x, lane = t & 31, wid = t >> 5;
    int warp_m = wid >> 2, warp_n = wid & 3;
    int bh = blockIdx.x, c0 = blockIdx.y << 6;

    // load q tile (hi/lo): 64 rows x 128 e -> 1024 ushort4 each
    #pragma unroll
    for (int it = 0; it < 4; it++) {
        int idx = t + (it << 8);
        int row = idx >> 4, u = idx & 15;
        size_t src = ((size_t)(bh * 256 + c0 + row)) * 128 + u * 8;
        uint32_t off = (uint32_t)(row * SROW + u * 8) * 2;
        *(uint4*)(smem + SQ_HI + off) = *(const uint4*)(g_qsh + src);
        *(uint4*)(smem + SQ_LO + off) = *(const uint4*)(g_qsl + src);
    }
    // load k full (hi/lo): 256 rows x 128 e -> 4096 ushort4 each
    #pragma unroll
    for (int it = 0; it < 16; it++) {
        int idx = t + (it << 8);
        int row = idx >> 4, u = idx & 15;
        size_t src = ((size_t)(bh * 256 + row)) * 128 + u * 8;
        uint32_t off = (uint32_t)(row * SROW + u * 8) * 2;
        *(uint4*)(smem + SK_HI + off) = *(const uint4*)(g_ksh + src);
        *(uint4*)(smem + SK_LO + off) = *(const uint4*)(g_ksl + src);
    }
    __syncthreads();

    float c[2][8][4];
    #pragma unroll
    for (int mb = 0; mb < 2; mb++)
        #pragma unroll
        for (int nb = 0; nb < 8; nb++)
            #pragma unroll
            for (int r = 0; r < 4; r++) c[mb][nb][r] = 0.f;

    int a_r = lane & 15;
    int a_c = (lane >> 4) << 3;
    int b_r = (lane & 7) | ((lane & 16) >> 1);
    int b_c = lane & 8;

    #pragma unroll
    for (int kk = 0; kk < 8; kk++) {
        int k0 = kk << 4;
        uint32_t a_hi[2][4], a_lo[2][4];
        #pragma unroll
        for (int mb = 0; mb < 2; mb++) {
            uint32_t off = (uint32_t)((warp_m * 32 + mb * 16 + a_r) * SROW + k0 + a_c) * 2;
            ldsm_x4(a_hi[mb], sb + SQ_HI + off);
            ldsm_x4(a_lo[mb], sb + SQ_LO + off);
        }
        uint32_t b_hi[8][2], b_lo[8][2];
        #pragma unroll
        for (int nb2 = 0; nb2 < 4; nb2++) {
            uint32_t off = (uint32_t)((warp_n * 64 + nb2 * 16 + b_r) * SROW + k0 + b_c) * 2;
            uint32_t r4[4];
            ldsm_x4(r4, sb + SK_HI + off);
            b_hi[nb2*2][0] = r4[0]; b_hi[nb2*2][1] = r4[1];
            b_hi[nb2*2+1][0] = r4[2]; b_hi[nb2*2+1][1] = r4[3];
            ldsm_x4(r4, sb + SK_LO + off);
            b_lo[nb2*2][0] = r4[0]; b_lo[nb2*2][1] = r4[1];
            b_lo[nb2*2+1][0] = r4[2]; b_lo[nb2*2+1][1] = r4[3];
        }
        #pragma unroll
        for (int mb = 0; mb < 2; mb++)
            #pragma unroll
            for (int nb = 0; nb < 8; nb++) {
                mma16816(c[mb][nb], a_hi[mb], b_hi[nb]);
                mma16816(c[mb][nb], a_hi[mb], b_lo[nb]);
                mma16816(c[mb][nb], a_lo[mb], b_hi[nb]);
            }
    }

    // rows owned by this thread: r(mb,half) = warp_m*32 + mb*16 + (lane>>2) + half*8
    float invd[2][2];
    #pragma unroll
    for (int mb = 0; mb < 2; mb++) {
        int rb = warp_m * 32 + mb * 16 + (lane >> 2);
        invd[mb][0] = g_invden[(size_t)bh * 256 + c0 + rb];
        invd[mb][1] = g_invden[(size_t)bh * 256 + c0 + rb + 8];
    }
    // scale by invden
    #pragma unroll
    for (int mb = 0; mb < 2; mb++)
        #pragma unroll
        for (int nb = 0; nb < 8; nb++) {
            c[mb][nb][0] *= invd[mb][0];
            c[mb][nb][1] *= invd[mb][0];
            c[mb][nb][2] *= invd[mb][1];
            c[mb][nb][3] *= invd[mb][1];
        }

    // row max: local over 8 nb x 2 vals, then shfl over lane bits 0-1, then cross-warp
    #pragma unroll
    for (int mb = 0; mb < 2; mb++)
        #pragma unroll
        for (int half = 0; half < 2; half++) {
            float mx = -INFINITY;
            #pragma unroll
            for (int nb = 0; nb < 8; nb++) {
                mx = fmaxf(mx, c[mb][nb][half*2+0]);
                mx = fmaxf(mx, c[mb][nb][half*2+1]);
            }
            mx = fmaxf(mx, __shfl_xor_sync(0xFFFFFFFFu, mx, 1));
            mx = fmaxf(mx, __shfl_xor_sync(0xFFFFFFFFu, mx, 2));
            if ((lane & 3) == 0) {
                int r = warp_m * 32 + mb * 16 + (lane >> 2) + half * 8;
                red[r * 8 + warp_n] = mx;
            }
        }
    __syncthreads();
    float bm[2][2];
    #pragma unroll
    for (int mb = 0; mb < 2; mb++)
        #pragma unroll
        for (int half = 0; half < 2; half++) {
            int r = warp_m * 32 + mb * 16 + (lane >> 2) + half * 8;
            float m0 = red[r * 8 + 0], m1 = red[r * 8 + 1];
            float m2 = red[r * 8 + 2], m3 = red[r * 8 + 3];
            bm[mb][half] = fmaxf(fmaxf(m0, m1), fmaxf(m2, m3));
        }
    // exp and row sum
    #pragma unroll
    for (int mb = 0; mb < 2; mb++)
        #pragma unroll
        for (int half = 0; half < 2; half++) {
            float s = 0.f;
            #pragma unroll
            for (int nb = 0; nb < 8; nb++) {
                float e0 = expf(c[mb][nb][half*2+0] - bm[mb][half]);
                float e1 = expf(c[mb][nb][half*2+1] - bm[mb][half]);
                c[mb][nb][half*2+0] = e0;
                c[mb][nb][half*2+1] = e1;
                s += e0 + e1;
            }
            s += __shfl_xor_sync(0xFFFFFFFFu, s, 1);
            s += __shfl_xor_sync(0xFFFFFFFFu, s, 2);
            if ((lane & 3) == 0) {
                int r = warp_m * 32 + mb * 16 + (lane >> 2) + half * 8;
                red[r * 8 + 4 + warp_n] = s;
            }
        }
    __syncthreads();
    #pragma unroll
    for (int mb = 0; mb < 2; mb++)
        #pragma unroll
        for (int half = 0; half < 2; half++) {
            int r = warp_m * 32 + mb * 16 + (lane >> 2) + half * 8;
            float tot = red[r * 8 + 4] + red[r * 8 + 5] + red[r * 8 + 6] + red[r * 8 + 7];
            float inv = 1.f / tot;
            size_t rowbase = ((size_t)bh * 256 + c0 + r) * 256;
            #pragma unroll
            for (int nb = 0; nb < 8; nb++) {
                int f = warp_n * 64 + nb * 8 + ((lane & 3) << 1);
                *(float2*)(g_scores + rowbase + f) =
                    make_float2(c[mb][nb][half*2+0] * inv, c[mb][nb][half*2+1] * inv);
            }
        }
}

// ---------------- att = weights @ v + residual ----------------
__global__ __launch_bounds__(256) void att_kernel(const float* __restrict__ x,
                                                  float* __restrict__ out) {
    __shared__ float Ash[64][33];
    __shared__ float Bsh[32][99];
    int t = threadIdx.x;
    int bh = blockIdx.x;
    int b = bh >> 3, h = bh & 7;
    int c0 = blockIdx.y << 6;
    const float* wrow = g_scores + ((size_t)bh * 256 + c0) * 256;
    const float* vb = g_vpool + ((size_t)b * 784 + h * 98) * 256;
    int tm = t & 31, tn = t >> 5;
    int dd[13];
    #pragma unroll
    for (int r = 0; r < 13; r++) {
        int d = tn + 8 * r;
        dd[r] = (d < 98) ? d : 0;
    }
    float acc[2][13];
    #pragma unroll
    for (int a_ = 0; a_ < 2; a_++)
        #pragma unroll
        for (int r = 0; r < 13; r++) acc[a_][r] = 0.f;

    int ar0 = t >> 3, aq0 = t & 7;
    for (int kc = 0; kc < 8; kc++) {
        int k0 = kc << 5;
        float4 av0 = *(const float4*)(wrow + (size_t)ar0 * 256 + k0 + (aq0 << 2));
        float4 av1 = *(const float4*)(wrow + (size_t)(ar0 + 32) * 256 + k0 + (aq0 << 2));
        float bstage[13];
        #pragma unroll
        for (int it = 0; it < 13; it++) {
            int idx = t + (it << 8);
            if (idx < 3136) {
                int kk = idx & 31, d = idx >> 5;
                bstage[it] = vb[(size_t)d * 256 + k0 + kk];
            }
        }
        __syncthreads();
        Ash[ar0][(aq0 << 2) + 0] = av0.x;
        Ash[ar0][(aq0 << 2) + 1] = av0.y;
        Ash[ar0][(aq0 << 2) + 2] = av0.z;
        Ash[ar0][(aq0 << 2) + 3] = av0.w;
        Ash[ar0 + 32][(aq0 << 2) + 0] = av1.x;
        Ash[ar0 + 32][(aq0 << 2) + 1] = av1.y;
        Ash[ar0 + 32][(aq0 << 2) + 2] = av1.z;
        Ash[ar0 + 32][(aq0 << 2) + 3] = av1.w;
        #pragma unroll
        for (int it = 0; it < 13; it++) {
            int idx = t + (it << 8);
            if (idx < 3136) Bsh[idx & 31][idx >> 5] = bstage[it];
        }
        __syncthreads();
        #pragma unroll
        for (int kk = 0; kk < 32; kk++) {
            float A0 = Ash[tm][kk], A1 = Ash[tm + 32][kk];
            #pragma unroll
            for (int r = 0; r < 13; r++) {
                float bb = Bsh[kk][dd[r]];
                acc[0][r] += A0 * bb;
                acc[1][r] += A1 * bb;
            }
        }
    }
    #pragma unroll
    for (int r = 0; r < 13; r++) {
        int d = tn + 8 * r;
        if (d < 98) {
            size_t o = ((size_t)b * 784 + h * 98 + d) * 256 + c0 + tm;
            out[o] = x[o] + acc[0][r];
            out[o + 32] = x[o + 32] + acc[1][r];
        }
    }
}

// ---------------- launch ----------------
extern "C" void kernel_launch(void* const* d_in, const int* in_sizes, int n_in,
                              void* d_out, int out_size) {
    const float* x     = (const float*)d_in[0];
    const float* wqk_w = (const float*)d_in[1];
    const float* wqk_b = (const float*)d_in[2];
    const float* wp_w  = (const float*)d_in[3];
    const float* wp_b  = (const float*)d_in[4];
    const float* wv_w  = (const float*)d_in[5];
    const float* wv_b  = (const float*)d_in[6];
    float* out = (float*)d_out;

    cudaFuncSetAttribute(conv_mma_kernel, cudaFuncAttributeMaxDynamicSharedMemorySize, CONV_SMEM);
    cudaFuncSetAttribute(scores_softmax_kernel, cudaFuncAttributeMaxDynamicSharedMemorySize, SS_SMEM);

    split_x_kernel<<<12544, 256>>>(x);
    split_w_kernel<<<2304, 256>>>(wv_w);
    conv_mma_kernel<<<dim3(392, 4), 256, CONV_SMEM>>>(wv_b);
    pool_qk_kernel<<<Bz * Ss, 256>>>(x);
    pool_v_kernel<<<Bz * Ss, 256>>>();
    proj_kernel<<<dim3(512, 4, 2), 256>>>(wqk_w, wqk_b, 0);
    proj_kernel<<<dim3(512, 4, 2), 256>>>(wqk_w, wqk_b, 1);
    temp_kernel<<<512, 256>>>(wp_w, wp_b);
    scores_softmax_kernel<<<dim3(512, 4), 256, SS_SMEM>>>();
    att_kernel<<<dim3(512, 4), 256>>>(x, out);
}

// round 9
// speedup vs baseline: 1.8635x; 1.0765x over previous
#include <cuda_runtime.h>
#include <cuda_bf16.h>
#include <cstdint>
#include <stdint.h>
#include <math.h>

#define Bz 64
#define Ss 784
#define Cc 256
#define Hh 8
#define BH 512

// ---------------- scratch ----------------
__device__ float g_qpool[Bz*Ss*Cc];
__device__ float g_kpool[Bz*Ss*Cc];
__device__ float g_vconv[Bz*Ss*Cc];
__device__ float g_q[BH*Cc*128];          // fp32 [bh][c][e] for temp
__device__ float g_k[BH*Cc*128];
__device__ float g_invden[BH*Cc];
// conv split operands
__device__ __nv_bfloat16 g_xh[Bz*Ss*Cc];
__device__ __nv_bfloat16 g_xl[Bz*Ss*Cc];
__device__ __nv_bfloat16 g_wth[Cc*2304];
__device__ __nv_bfloat16 g_wtl[Cc*2304];
// transposed pooled splits [bh][c][112] (d zero-padded >= 98)
__device__ __nv_bfloat16 g_qpTh[BH*Cc*112];
__device__ __nv_bfloat16 g_qpTl[BH*Cc*112];
__device__ __nv_bfloat16 g_kpTh[BH*Cc*112];
__device__ __nv_bfloat16 g_kpTl[BH*Cc*112];
// transposed wqk splits [h][e=128][112]
__device__ __nv_bfloat16 g_wqkTh[Hh*128*112];
__device__ __nv_bfloat16 g_wqkTl[Hh*128*112];
// q/k splits [bh][c][128] for scores
__device__ __nv_bfloat16 g_qsh[BH*Cc*128];
__device__ __nv_bfloat16 g_qsl[BH*Cc*128];
__device__ __nv_bfloat16 g_ksh[BH*Cc*128];
__device__ __nv_bfloat16 g_ksl[BH*Cc*128];
// normalized attention weights splits [bh][c][f]
__device__ __nv_bfloat16 g_wh[(size_t)BH*Cc*Cc];
__device__ __nv_bfloat16 g_wl[(size_t)BH*Cc*Cc];
// pooled v splits [b*784+s][c], padded for att row overrun
__device__ __nv_bfloat16 g_vph[Bz*Ss*Cc + 8192];
__device__ __nv_bfloat16 g_vpl[Bz*Ss*Cc + 8192];

// ---------------- helpers ----------------
__device__ __forceinline__ uint32_t smem_u32(const void* p) {
    uint32_t a;
    asm("{ .reg .u64 t; cvta.to.shared.u64 t, %1; cvt.u32.u64 %0, t; }" : "=r"(a) : "l"(p));
    return a;
}
__device__ __forceinline__ void cp16(uint32_t dst, const void* src, uint32_t srcsize) {
    asm volatile("cp.async.cg.shared.global [%0], [%1], 16, %2;"
                 :: "r"(dst), "l"(src), "r"(srcsize) : "memory");
}
__device__ __forceinline__ void ldsm_x4(uint32_t* r, uint32_t addr) {
    asm volatile("ldmatrix.sync.aligned.m8n8.x4.shared.b16 {%0,%1,%2,%3}, [%4];"
                 : "=r"(r[0]), "=r"(r[1]), "=r"(r[2]), "=r"(r[3]) : "r"(addr));
}
__device__ __forceinline__ void mma16816(float* c, const uint32_t* a, const uint32_t* b) {
    asm volatile("mma.sync.aligned.m16n8k16.row.col.f32.bf16.bf16.f32 "
                 "{%0,%1,%2,%3}, {%4,%5,%6,%7}, {%8,%9}, {%0,%1,%2,%3};"
                 : "+f"(c[0]), "+f"(c[1]), "+f"(c[2]), "+f"(c[3])
                 : "r"(a[0]), "r"(a[1]), "r"(a[2]), "r"(a[3]), "r"(b[0]), "r"(b[1]));
}
__device__ __forceinline__ void split2(float v, __nv_bfloat16& h, __nv_bfloat16& l) {
    h = __float2bfloat16(v);
    l = __float2bfloat16(v - __bfloat162float(h));
}
__device__ __forceinline__ uint32_t pack2(float v0, float v1, uint32_t& lo) {
    __nv_bfloat16 h0, h1, l0, l1;
    split2(v0, h0, l0); split2(v1, h1, l1);
    lo = (uint32_t)__bfloat16_as_ushort(l0) | ((uint32_t)__bfloat16_as_ushort(l1) << 16);
    return (uint32_t)__bfloat16_as_ushort(h0) | ((uint32_t)__bfloat16_as_ushort(h1) << 16);
}

// ---------------- conv prep ----------------
__global__ __launch_bounds__(256) void split_x_kernel(const float* __restrict__ x) {
    int idx4 = blockIdx.x * 256 + threadIdx.x;
    float4 v = ((const float4*)x)[idx4];
    uint32_t l01, l23;
    uint32_t h01 = pack2(v.x, v.y, l01);
    uint32_t h23 = pack2(v.z, v.w, l23);
    ((uint2*)g_xh)[idx4] = make_uint2(h01, h23);
    ((uint2*)g_xl)[idx4] = make_uint2(l01, l23);
}

__global__ __launch_bounds__(256) void split_w_kernel(const float* __restrict__ w) {
    int k = blockIdx.x;
    int co = threadIdx.x;
    float v = w[(size_t)k * 256 + co];
    __nv_bfloat16 h, l;
    split2(v, h, l);
    g_wth[(size_t)co * 2304 + k] = h;
    g_wtl[(size_t)co * 2304 + k] = l;
}

// ---------------- conv mma ----------------
#define CROW 72
#define CA_HI 0
#define CA_LO 18432
#define CB_HI 36864
#define CB_LO 46080
#define CSTAGE 55296
#define CONV_SMEM (2*CSTAGE)

__device__ __forceinline__ void conv_load_stage(
    int s, uint32_t sb, int arow, int ahalf, int bb, int pi, int pj,
    int brow, int bq, int n0g)
{
    uint32_t bufo = sb + (uint32_t)(s & 1) * CSTAGE;
    int tap = s >> 2;
    int di = tap / 3, dj = tap - di * 3;
    int ii = pi + di - 1, jj = pj + dj - 1;
    bool valid = ((unsigned)ii < 28u) && ((unsigned)jj < 28u);
    int ci0 = ((s & 3) << 6) + ahalf * 32;
    size_t ga = ((size_t)(bb * 784 + (valid ? ii * 28 + jj : 0)) << 8) + ci0;
    uint32_t rowoff = (uint32_t)(arow * CROW + ahalf * 32) * 2;
    uint32_t vs = valid ? 16u : 0u;
    #pragma unroll
    for (int q = 0; q < 4; q++) {
        cp16(bufo + CA_HI + rowoff + q * 16, g_xh + ga + q * 8, vs);
        cp16(bufo + CA_LO + rowoff + q * 16, g_xl + ga + q * 8, vs);
    }
    size_t gb = (size_t)(n0g + brow) * 2304 + (size_t)s * 64 + bq * 16;
    uint32_t boff = (uint32_t)(brow * CROW + bq * 16) * 2;
    cp16(bufo + CB_HI + boff,      g_wth + gb,     16u);
    cp16(bufo + CB_HI + boff + 16, g_wth + gb + 8, 16u);
    cp16(bufo + CB_LO + boff,      g_wtl + gb,     16u);
    cp16(bufo + CB_LO + boff + 16, g_wtl + gb + 8, 16u);
    asm volatile("cp.async.commit_group;" ::: "memory");
}

__global__ __launch_bounds__(256) void conv_mma_kernel(const float* __restrict__ bias) {
    extern __shared__ char smem[];
    uint32_t sb = smem_u32(smem);
    int t = threadIdx.x, lane = t & 31, wid = t >> 5;
    int warp_m = wid >> 1, warp_n = wid & 1;
    int m0 = blockIdx.x << 7;
    int n0g = blockIdx.y << 6;

    int arow = t >> 1, ahalf = t & 1;
    int m = m0 + arow;
    int bb = m / 784;
    int pix = m - bb * 784;
    int pi = pix / 28, pj = pix - pi * 28;
    int brow = t >> 2, bq = t & 3;

    float c[2][4][4];
    #pragma unroll
    for (int mb = 0; mb < 2; mb++)
        #pragma unroll
        for (int nb = 0; nb < 4; nb++)
            #pragma unroll
            for (int r = 0; r < 4; r++) c[mb][nb][r] = 0.f;

    int a_r = lane & 15;
    int a_c = (lane >> 4) << 3;
    int b_r = (lane & 7) | ((lane & 16) >> 1);
    int b_c = lane & 8;

    conv_load_stage(0, sb, arow, ahalf, bb, pi, pj, brow, bq, n0g);

    for (int s = 0; s < 36; s++) {
        if (s + 1 < 36) {
            conv_load_stage(s + 1, sb, arow, ahalf, bb, pi, pj, brow, bq, n0g);
            asm volatile("cp.async.wait_group 1;" ::: "memory");
        } else {
            asm volatile("cp.async.wait_group 0;" ::: "memory");
        }
        __syncthreads();

        uint32_t bufo = sb + (uint32_t)(s & 1) * CSTAGE;
        #pragma unroll
        for (int kk = 0; kk < 4; kk++) {
            int k0 = kk << 4;
            uint32_t a_hi[2][4], a_lo[2][4];
            #pragma unroll
            for (int mb = 0; mb < 2; mb++) {
                uint32_t off = (uint32_t)((warp_m * 32 + mb * 16 + a_r) * CROW + k0 + a_c) * 2;
                ldsm_x4(a_hi[mb], bufo + CA_HI + off);
                ldsm_x4(a_lo[mb], bufo + CA_LO + off);
            }
            uint32_t b_hi[4][2], b_lo[4][2];
            #pragma unroll
            for (int nb2 = 0; nb2 < 2; nb2++) {
                uint32_t off = (uint32_t)((warp_n * 32 + nb2 * 16 + b_r) * CROW + k0 + b_c) * 2;
                uint32_t r4[4];
                ldsm_x4(r4, bufo + CB_HI + off);
                b_hi[nb2*2][0] = r4[0]; b_hi[nb2*2][1] = r4[1];
                b_hi[nb2*2+1][0] = r4[2]; b_hi[nb2*2+1][1] = r4[3];
                ldsm_x4(r4, bufo + CB_LO + off);
                b_lo[nb2*2][0] = r4[0]; b_lo[nb2*2][1] = r4[1];
                b_lo[nb2*2+1][0] = r4[2]; b_lo[nb2*2+1][1] = r4[3];
            }
            #pragma unroll
            for (int mb = 0; mb < 2; mb++)
                #pragma unroll
                for (int nb = 0; nb < 4; nb++) {
                    mma16816(c[mb][nb], a_hi[mb], b_hi[nb]);
                    mma16816(c[mb][nb], a_hi[mb], b_lo[nb]);
                    mma16816(c[mb][nb], a_lo[mb], b_hi[nb]);
                }
        }
        __syncthreads();
    }

    #pragma unroll
    for (int mb = 0; mb < 2; mb++) {
        int rg = m0 + warp_m * 32 + mb * 16 + (lane >> 2);
        #pragma unroll
        for (int nb = 0; nb < 4; nb++) {
            int cg = n0g + warp_n * 32 + nb * 8 + ((lane & 3) << 1);
            float2 bz = *(const float2*)(bias + cg);
            *(float2*)(g_vconv + (size_t)rg * 256 + cg) =
                make_float2(c[mb][nb][0] + bz.x, c[mb][nb][1] + bz.y);
            *(float2*)(g_vconv + (size_t)(rg + 8) * 256 + cg) =
                make_float2(c[mb][nb][2] + bz.x, c[mb][nb][3] + bz.y);
        }
    }
}

// ---------------- pooling ----------------
__global__ __launch_bounds__(256) void pool_qk_kernel(const float* __restrict__ x) {
    int bs = blockIdx.x;
    int c  = threadIdx.x;
    int b  = bs / 784;
    int pix = bs - b * 784;
    int i = pix / 28, j = pix - i * 28;
    const float* xb = x + (size_t)b * 784 * 256;
    float sum = 0.f, mx = -INFINITY;
    int cnt = 0;
    #pragma unroll
    for (int di = -1; di <= 1; di++) {
        #pragma unroll
        for (int dj = -1; dj <= 1; dj++) {
            int ii = i + di, jj = j + dj;
            if ((unsigned)ii < 28u && (unsigned)jj < 28u) {
                float v = xb[(size_t)(ii * 28 + jj) * 256 + c];
                sum += v;
                mx = fmaxf(mx, v);
                cnt++;
            }
        }
    }
    size_t o = (size_t)bs * 256 + c;
    g_qpool[o] = sum / (float)cnt;
    g_kpool[o] = mx;
}

__global__ __launch_bounds__(256) void pool_v_kernel() {
    int bs = blockIdx.x;
    int c  = threadIdx.x;
    int b  = bs / 784;
    int pix = bs - b * 784;
    int i = pix / 28, j = pix - i * 28;
    const float* xb = g_vconv + (size_t)b * 784 * 256;
    float sum = 0.f;
    int cnt = 0;
    #pragma unroll
    for (int di = -1; di <= 1; di++) {
        #pragma unroll
        for (int dj = -1; dj <= 1; dj++) {
            int ii = i + di, jj = j + dj;
            if ((unsigned)ii < 28u && (unsigned)jj < 28u) {
                sum += xb[(size_t)(ii * 28 + jj) * 256 + c];
                cnt++;
            }
        }
    }
    __nv_bfloat16 h, l;
    split2(sum / (float)cnt, h, l);
    size_t o = (size_t)bs * 256 + c;
    g_vph[o] = h;
    g_vpl[o] = l;
}

// ---------------- pool transpose+split ----------------
__global__ __launch_bounds__(256) void poolT_kernel() {
    __shared__ float tile[32][33];
    int bh = blockIdx.x;
    int which = blockIdx.y;
    int b = bh >> 3, h = bh & 7;
    const float* src = (which ? g_kpool : g_qpool) + ((size_t)b * 784 + h * 98) * 256;
    __nv_bfloat16* dsth = which ? g_kpTh : g_qpTh;
    __nv_bfloat16* dstl = which ? g_kpTl : g_qpTl;
    int t = threadIdx.x;
    int r8 = t >> 5, cl = t & 31;
    for (int dt = 0; dt < 4; dt++) {
        int d0 = dt << 5;
        for (int ct = 0; ct < 8; ct++) {
            int c0 = ct << 5;
            #pragma unroll
            for (int p = 0; p < 4; p++) {
                int dl = r8 + p * 8;
                int d = d0 + dl;
                tile[dl][cl] = (d < 98) ? src[(size_t)d * 256 + c0 + cl] : 0.f;
            }
            __syncthreads();
            #pragma unroll
            for (int p = 0; p < 4; p++) {
                int cr = r8 + p * 8;
                int d = d0 + cl;
                if (d < 112) {
                    __nv_bfloat16 hh, ll;
                    split2(tile[cl][cr], hh, ll);
                    size_t o = ((size_t)bh * 256 + c0 + cr) * 112 + d;
                    dsth[o] = hh;
                    dstl[o] = ll;
                }
            }
            __syncthreads();
        }
    }
}

// ---------------- wqk transpose+split ----------------
__global__ __launch_bounds__(128) void wqkT_kernel(const float* __restrict__ wqk) {
    int h = blockIdx.x;
    int e = threadIdx.x;
    for (int d = 0; d < 112; d++) {
        float v = (d < 98) ? wqk[((size_t)h * 98 + d) * 128 + e] : 0.f;
        __nv_bfloat16 hh, ll;
        split2(v, hh, ll);
        size_t o = ((size_t)h * 128 + e) * 112 + d;
        g_wqkTh[o] = hh;
        g_wqkTl[o] = ll;
    }
}

// ---------------- proj mma: per (bh, chalf, which): M=128(c) N=128(e) K=112(d) ----------------
#define PROW 120
#define PA_HI 0
#define PA_LO 30720
#define PB_HI 61440
#define PB_LO 92160
#define PROJ_SMEM 122880

__global__ __launch_bounds__(256) void proj_mma_kernel(const float* __restrict__ bias) {
    extern __shared__ char smem[];
    uint32_t sb = smem_u32(smem);
    int t = threadIdx.x, lane = t & 31, wid = t >> 5;
    int warp_m = wid >> 1, warp_n = wid & 1;
    int bh = blockIdx.x, chalf = blockIdx.y, which = blockIdx.z;
    int h = bh & 7;
    const __nv_bfloat16* Ah = (which ? g_kpTh : g_qpTh) + ((size_t)bh * 256 + chalf * 128) * 112;
    const __nv_bfloat16* Al = (which ? g_kpTl : g_qpTl) + ((size_t)bh * 256 + chalf * 128) * 112;
    const __nv_bfloat16* Bh = g_wqkTh + (size_t)h * 128 * 112;
    const __nv_bfloat16* Bl = g_wqkTl + (size_t)h * 128 * 112;
    float* outf = which ? g_k : g_q;
    __nv_bfloat16* outh = which ? g_ksh : g_qsh;
    __nv_bfloat16* outl = which ? g_ksl : g_qsl;

    #pragma unroll
    for (int it = 0; it < 7; it++) {
        int idx = t + (it << 8);
        int row = idx / 14, ch = idx - row * 14;
        uint32_t doff = (uint32_t)(row * PROW * 2 + ch * 16);
        cp16(sb + PA_HI + doff, Ah + (size_t)row * 112 + ch * 8, 16u);
        cp16(sb + PA_LO + doff, Al + (size_t)row * 112 + ch * 8, 16u);
        cp16(sb + PB_HI + doff, Bh + (size_t)row * 112 + ch * 8, 16u);
        cp16(sb + PB_LO + doff, Bl + (size_t)row * 112 + ch * 8, 16u);
    }
    asm volatile("cp.async.commit_group;" ::: "memory");
    asm volatile("cp.async.wait_group 0;" ::: "memory");
    __syncthreads();

    float c[2][8][4];
    #pragma unroll
    for (int mb = 0; mb < 2; mb++)
        #pragma unroll
        for (int nb = 0; nb < 8; nb++)
            #pragma unroll
            for (int r = 0; r < 4; r++) c[mb][nb][r] = 0.f;

    int a_r = lane & 15;
    int a_c = (lane >> 4) << 3;
    int b_r = (lane & 7) | ((lane & 16) >> 1);
    int b_c = lane & 8;

    #pragma unroll
    for (int kk = 0; kk < 7; kk++) {
        int k0 = kk << 4;
        uint32_t a_hi[2][4], a_lo[2][4];
        #pragma unroll
        for (int mb = 0; mb < 2; mb++) {
            uint32_t off = (uint32_t)((warp_m * 32 + mb * 16 + a_r) * PROW + k0 + a_c) * 2;
            ldsm_x4(a_hi[mb], sb + PA_HI + off);
            ldsm_x4(a_lo[mb], sb + PA_LO + off);
        }
        uint32_t b_hi[8][2], b_lo[8][2];
        #pragma unroll
        for (int nb2 = 0; nb2 < 4; nb2++) {
            uint32_t off = (uint32_t)((warp_n * 64 + nb2 * 16 + b_r) * PROW + k0 + b_c) * 2;
            uint32_t r4[4];
            ldsm_x4(r4, sb + PB_HI + off);
            b_hi[nb2*2][0] = r4[0]; b_hi[nb2*2][1] = r4[1];
            b_hi[nb2*2+1][0] = r4[2]; b_hi[nb2*2+1][1] = r4[3];
            ldsm_x4(r4, sb + PB_LO + off);
            b_lo[nb2*2][0] = r4[0]; b_lo[nb2*2][1] = r4[1];
            b_lo[nb2*2+1][0] = r4[2]; b_lo[nb2*2+1][1] = r4[3];
        }
        #pragma unroll
        for (int mb = 0; mb < 2; mb++)
            #pragma unroll
            for (int nb = 0; nb < 8; nb++) {
                mma16816(c[mb][nb], a_hi[mb], b_hi[nb]);
                mma16816(c[mb][nb], a_hi[mb], b_lo[nb]);
                mma16816(c[mb][nb], a_lo[mb], b_hi[nb]);
            }
    }

    #pragma unroll
    for (int mb = 0; mb < 2; mb++) {
        #pragma unroll
        for (int half = 0; half < 2; half++) {
            int cr = chalf * 128 + warp_m * 32 + mb * 16 + (lane >> 2) + half * 8;
            size_t rowo = ((size_t)bh * 256 + cr) * 128;
            #pragma unroll
            for (int nb = 0; nb < 8; nb++) {
                int e = warp_n * 64 + nb * 8 + ((lane & 3) << 1);
                float2 bz = *(const float2*)(bias + h * 128 + e);
                float v0 = c[mb][nb][half*2+0] + bz.x;
                float v1 = c[mb][nb][half*2+1] + bz.y;
                *(float2*)(outf + rowo + e) = make_float2(v0, v1);
                uint32_t lo;
                uint32_t hi = pack2(v0, v1, lo);
                *(uint32_t*)(outh + rowo + e) = hi;
                *(uint32_t*)(outl + rowo + e) = lo;
            }
        }
    }
}

// ---------------- temperature ----------------
__global__ __launch_bounds__(256) void temp_kernel(const float* __restrict__ wp_w,
                                                   const float* __restrict__ wp_b) {
    __shared__ float kbar[128];
    __shared__ float rowmean[256];
    int bh = blockIdx.x;
    int t = threadIdx.x;
    const float* kb = g_k + (size_t)bh * Cc * 128;
    const float* qb = g_q + (size_t)bh * Cc * 128;
    if (t < 128) {
        float s = 0.f;
        for (int f = 0; f < 256; f++) s += kb[(size_t)f * 128 + t];
        kbar[t] = s * (1.f / 256.f);
    }
    __syncthreads();
    int w = t >> 5, lane = t & 31;
    float4 kv = *(const float4*)&kbar[lane << 2];
    for (int r = 0; r < 32; r++) {
        int c = (w << 5) + r;
        float4 qv = *(const float4*)(qb + (size_t)c * 128 + (lane << 2));
        float p = qv.x * kv.x + qv.y * kv.y + qv.z * kv.z + qv.w * kv.w;
        #pragma unroll
        for (int o = 16; o; o >>= 1) p += __shfl_xor_sync(0xFFFFFFFFu, p, o);
        if (lane == 0) rowmean[c] = p;
    }
    __syncthreads();
    float s = wp_b[t];
    for (int cc = 0; cc < 256; cc++) s += rowmean[cc] * wp_w[(size_t)cc * 256 + t];
    float sig = 1.f / (1.f + expf(-s));
    g_invden[(size_t)bh * 256 + t] = exp2f(-7.f * (0.2f + sig));
}

// ---------------- fused scores + softmax -> bf16 weight splits ----------------
#define SROW 136
#define SQ_HI 0
#define SQ_LO 17408
#define SK_HI 34816
#define SK_LO 104448
#define SRED  174080
#define SS_SMEM 176128

__global__ __launch_bounds__(256) void scores_softmax_kernel() {
    extern __shared__ char smem[];
    uint32_t sb = smem_u32(smem);
    float* red = (float*)(smem + SRED);
    int t = threadIdx.x, lane = t & 31, wid = t >> 5;
    int warp_m = wid >> 2, warp_n = wid & 3;
    int bh = blockIdx.x, c0 = blockIdx.y << 6;

    #pragma unroll
    for (int it = 0; it < 4; it++) {
        int idx = t + (it << 8);
        int row = idx >> 4, u = idx & 15;
        size_t src = ((size_t)(bh * 256 + c0 + row)) * 128 + u * 8;
        uint32_t off = (uint32_t)(row * SROW + u * 8) * 2;
        *(uint4*)(smem + SQ_HI + off) = *(const uint4*)(g_qsh + src);
        *(uint4*)(smem + SQ_LO + off) = *(const uint4*)(g_qsl + src);
    }
    #pragma unroll
    for (int it = 0; it < 16; it++) {
        int idx = t + (it << 8);
        int row = idx >> 4, u = idx & 15;
        size_t src = ((size_t)(bh * 256 + row)) * 128 + u * 8;
        uint32_t off = (uint32_t)(row * SROW + u * 8) * 2;
        *(uint4*)(smem + SK_HI + off) = *(const uint4*)(g_ksh + src);
        *(uint4*)(smem + SK_LO + off) = *(const uint4*)(g_ksl + src);
    }
    __syncthreads();

    float c[2][8][4];
    #pragma unroll
    for (int mb = 0; mb < 2; mb++)
        #pragma unroll
        for (int nb = 0; nb < 8; nb++)
            #pragma unroll
            for (int r = 0; r < 4; r++) c[mb][nb][r] = 0.f;

    int a_r = lane & 15;
    int a_c = (lane >> 4) << 3;
    int b_r = (lane & 7) | ((lane & 16) >> 1);
    int b_c = lane & 8;

    #pragma unroll
    for (int kk = 0; kk < 8; kk++) {
        int k0 = kk << 4;
        uint32_t a_hi[2][4], a_lo[2][4];
        #pragma unroll
        for (int mb = 0; mb < 2; mb++) {
            uint32_t off = (uint32_t)((warp_m * 32 + mb * 16 + a_r) * SROW + k0 + a_c) * 2;
            ldsm_x4(a_hi[mb], sb + SQ_HI + off);
            ldsm_x4(a_lo[mb], sb + SQ_LO + off);
        }
        uint32_t b_hi[8][2], b_lo[8][2];
        #pragma unroll
        for (int nb2 = 0; nb2 < 4; nb2++) {
            uint32_t off = (uint32_t)((warp_n * 64 + nb2 * 16 + b_r) * SROW + k0 + b_c) * 2;
            uint32_t r4[4];
            ldsm_x4(r4, sb + SK_HI + off);
            b_hi[nb2*2][0] = r4[0]; b_hi[nb2*2][1] = r4[1];
            b_hi[nb2*2+1][0] = r4[2]; b_hi[nb2*2+1][1] = r4[3];
            ldsm_x4(r4, sb + SK_LO + off);
            b_lo[nb2*2][0] = r4[0]; b_lo[nb2*2][1] = r4[1];
            b_lo[nb2*2+1][0] = r4[2]; b_lo[nb2*2+1][1] = r4[3];
        }
        #pragma unroll
        for (int mb = 0; mb < 2; mb++)
            #pragma unroll
            for (int nb = 0; nb < 8; nb++) {
                mma16816(c[mb][nb], a_hi[mb], b_hi[nb]);
                mma16816(c[mb][nb], a_hi[mb], b_lo[nb]);
                mma16816(c[mb][nb], a_lo[mb], b_hi[nb]);
            }
    }

    float invd[2][2];
    #pragma unroll
    for (int mb = 0; mb < 2; mb++) {
        int rb = warp_m * 32 + mb * 16 + (lane >> 2);
        invd[mb][0] = g_invden[(size_t)bh * 256 + c0 + rb];
        invd[mb][1] = g_invden[(size_t)bh * 256 + c0 + rb + 8];
    }
    #pragma unroll
    for (int mb = 0; mb < 2; mb++)
        #pragma unroll
        for (int nb = 0; nb < 8; nb++) {
            c[mb][nb][0] *= invd[mb][0];
            c[mb][nb][1] *= invd[mb][0];
            c[mb][nb][2] *= invd[mb][1];
            c[mb][nb][3] *= invd[mb][1];
        }

    #pragma unroll
    for (int mb = 0; mb < 2; mb++)
        #pragma unroll
        for (int half = 0; half < 2; half++) {
            float mx = -INFINITY;
            #pragma unroll
            for (int nb = 0; nb < 8; nb++) {
                mx = fmaxf(mx, c[mb][nb][half*2+0]);
                mx = fmaxf(mx, c[mb][nb][half*2+1]);
            }
            mx = fmaxf(mx, __shfl_xor_sync(0xFFFFFFFFu, mx, 1));
            mx = fmaxf(mx, __shfl_xor_sync(0xFFFFFFFFu, mx, 2));
            if ((lane & 3) == 0) {
                int r = warp_m * 32 + mb * 16 + (lane >> 2) + half * 8;
                red[r * 8 + warp_n] = mx;
            }
        }
    __syncthreads();
    float bm[2][2];
    #pragma unroll
    for (int mb = 0; mb < 2; mb++)
        #pragma unroll
        for (int half = 0; half < 2; half++) {
            int r = warp_m * 32 + mb * 16 + (lane >> 2) + half * 8;
            bm[mb][half] = fmaxf(fmaxf(red[r*8+0], red[r*8+1]), fmaxf(red[r*8+2], red[r*8+3]));
        }
    #pragma unroll
    for (int mb = 0; mb < 2; mb++)
        #pragma unroll
        for (int half = 0; half < 2; half++) {
            float s = 0.f;
            #pragma unroll
            for (int nb = 0; nb < 8; nb++) {
                float e0 = expf(c[mb][nb][half*2+0] - bm[mb][half]);
                float e1 = expf(c[mb][nb][half*2+1] - bm[mb][half]);
                c[mb][nb][half*2+0] = e0;
                c[mb][nb][half*2+1] = e1;
                s += e0 + e1;
            }
            s += __shfl_xor_sync(0xFFFFFFFFu, s, 1);
            s += __shfl_xor_sync(0xFFFFFFFFu, s, 2);
            if ((lane & 3) == 0) {
                int r = warp_m * 32 + mb * 16 + (lane >> 2) + half * 8;
                red[r * 8 + 4 + warp_n] = s;
            }
        }
    __syncthreads();
    #pragma unroll
    for (int mb = 0; mb < 2; mb++)
        #pragma unroll
        for (int half = 0; half < 2; half++) {
            int r = warp_m * 32 + mb * 16 + (lane >> 2) + half * 8;
            float tot = red[r*8+4] + red[r*8+5] + red[r*8+6] + red[r*8+7];
            float inv = 1.f / tot;
            size_t rowbase = ((size_t)bh * 256 + c0 + r) * 256;
            #pragma unroll
            for (int nb = 0; nb < 8; nb++) {
                int f = warp_n * 64 + nb * 8 + ((lane & 3) << 1);
                uint32_t lo;
                uint32_t hi = pack2(c[mb][nb][half*2+0] * inv, c[mb][nb][half*2+1] * inv, lo);
                *(uint32_t*)(g_wh + rowbase + f) = hi;
                *(uint32_t*)(g_wl + rowbase + f) = lo;
            }
        }
}

// ---------------- att mma (transposed): per (bh, chalf): M=128(d) N=128(c) K=256(f) ----------------
#define AROW 72
#define AA_HI 0
#define AA_LO 18432
#define AB_HI 36864
#define AB_LO 55296
#define ASTAGE 73728
#define ATT_SMEM (2*ASTAGE)

__device__ __forceinline__ void att_load_stage(
    uint32_t bufo, int f0, size_t abase, size_t bbase, int lrow, int lch)
{
    #pragma unroll
    for (int p = 0; p < 4; p++) {
        int row = lrow + p * 32;
        size_t asrc = abase + (size_t)row * 256 + f0 + lch * 8;
        size_t bsrc = bbase + (size_t)row * 256 + f0 + lch * 8;
        uint32_t doff = (uint32_t)(row * AROW + lch * 8) * 2;
        cp16(bufo + AA_HI + doff, g_vph + asrc, 16u);
        cp16(bufo + AA_LO + doff, g_vpl + asrc, 16u);
        cp16(bufo + AB_HI + doff, g_wh + bsrc, 16u);
        cp16(bufo + AB_LO + doff, g_wl + bsrc, 16u);
    }
    asm volatile("cp.async.commit_group;" ::: "memory");
}

__global__ __launch_bounds__(256) void att_mma_kernel(const float* __restrict__ x,
                                                      float* __restrict__ out) {
    extern __shared__ char smem[];
    uint32_t sb = smem_u32(smem);
    int t = threadIdx.x, lane = t & 31, wid = t >> 5;
    int warp_m = wid >> 1, warp_n = wid & 1;
    int bh = blockIdx.x, chalf = blockIdx.y;
    int b = bh >> 3, h = bh & 7;
    size_t abase = ((size_t)b * 784 + h * 98) * 256;
    size_t bbase = ((size_t)bh * 256 + chalf * 128) * 256;

    int lrow = t >> 3, lch = t & 7;   // lrow 0..31, lch 0..7

    att_load_stage(sb, 0, abase, bbase, lrow, lch);

    float c[2][8][4];
    #pragma unroll
    for (int mb = 0; mb < 2; mb++)
        #pragma unroll
        for (int nb = 0; nb < 8; nb++)
            #pragma unroll
            for (int r = 0; r < 4; r++) c[mb][nb][r] = 0.f;

    int a_r = lane & 15;
    int a_c = (lane >> 4) << 3;
    int b_r = (lane & 7) | ((lane & 16) >> 1);
    int b_c = lane & 8;

    for (int s = 0; s < 4; s++) {
        if (s + 1 < 4) {
            att_load_stage(sb + (uint32_t)((s + 1) & 1) * ASTAGE, (s + 1) << 6,
                           abase, bbase, lrow, lch);
            asm volatile("cp.async.wait_group 1;" ::: "memory");
        } else {
            asm volatile("cp.async.wait_group 0;" ::: "memory");
        }
        __syncthreads();

        uint32_t bufo = sb + (uint32_t)(s & 1) * ASTAGE;
        #pragma unroll
        for (int kk = 0; kk < 4; kk++) {
            int k0 = kk << 4;
            uint32_t a_hi[2][4], a_lo[2][4];
            #pragma unroll
            for (int mb = 0; mb < 2; mb++) {
                uint32_t off = (uint32_t)((warp_m * 32 + mb * 16 + a_r) * AROW + k0 + a_c) * 2;
                ldsm_x4(a_hi[mb], bufo + AA_HI + off);
                ldsm_x4(a_lo[mb], bufo + AA_LO + off);
            }
            uint32_t b_hi[8][2], b_lo[8][2];
            #pragma unroll
            for (int nb2 = 0; nb2 < 4; nb2++) {
                uint32_t off = (uint32_t)((warp_n * 64 + nb2 * 16 + b_r) * AROW + k0 + b_c) * 2;
                uint32_t r4[4];
                ldsm_x4(r4, bufo + AB_HI + off);
                b_hi[nb2*2][0] = r4[0]; b_hi[nb2*2][1] = r4[1];
                b_hi[nb2*2+1][0] = r4[2]; b_hi[nb2*2+1][1] = r4[3];
                ldsm_x4(r4, bufo + AB_LO + off);
                b_lo[nb2*2][0] = r4[0]; b_lo[nb2*2][1] = r4[1];
                b_lo[nb2*2+1][0] = r4[2]; b_lo[nb2*2+1][1] = r4[3];
            }
            #pragma unroll
            for (int mb = 0; mb < 2; mb++)
                #pragma unroll
                for (int nb = 0; nb < 8; nb++) {
                    mma16816(c[mb][nb], a_hi[mb], b_hi[nb]);
                    mma16816(c[mb][nb], a_hi[mb], b_lo[nb]);
                    mma16816(c[mb][nb], a_lo[mb], b_hi[nb]);
                }
        }
        __syncthreads();
    }

    #pragma unroll
    for (int mb = 0; mb < 2; mb++)
        #pragma unroll
        for (int half = 0; half < 2; half++) {
            int d = warp_m * 32 + mb * 16 + (lane >> 2) + half * 8;
            if (d < 98) {
                size_t rowo = abase + (size_t)d * 256 + chalf * 128;
                #pragma unroll
                for (int nb = 0; nb < 8; nb++) {
                    int cg = warp_n * 64 + nb * 8 + ((lane & 3) << 1);
                    float2 xv = *(const float2*)(x + rowo + cg);
                    *(float2*)(out + rowo + cg) =
                        make_float2(xv.x + c[mb][nb][half*2+0], xv.y + c[mb][nb][half*2+1]);
                }
            }
        }
}

// ---------------- launch ----------------
extern "C" void kernel_launch(void* const* d_in, const int* in_sizes, int n_in,
                              void* d_out, int out_size) {
    const float* x     = (const float*)d_in[0];
    const float* wqk_w = (const float*)d_in[1];
    const float* wqk_b = (const float*)d_in[2];
    const float* wp_w  = (const float*)d_in[3];
    const float* wp_b  = (const float*)d_in[4];
    const float* wv_w  = (const float*)d_in[5];
    const float* wv_b  = (const float*)d_in[6];
    float* out = (float*)d_out;

    cudaFuncSetAttribute(conv_mma_kernel, cudaFuncAttributeMaxDynamicSharedMemorySize, CONV_SMEM);
    cudaFuncSetAttribute(scores_softmax_kernel, cudaFuncAttributeMaxDynamicSharedMemorySize, SS_SMEM);
    cudaFuncSetAttribute(proj_mma_kernel, cudaFuncAttributeMaxDynamicSharedMemorySize, PROJ_SMEM);
    cudaFuncSetAttribute(att_mma_kernel, cudaFuncAttributeMaxDynamicSharedMemorySize, ATT_SMEM);

    split_x_kernel<<<12544, 256>>>(x);
    split_w_kernel<<<2304, 256>>>(wv_w);
    conv_mma_kernel<<<dim3(392, 4), 256, CONV_SMEM>>>(wv_b);
    pool_qk_kernel<<<Bz * Ss, 256>>>(x);
    pool_v_kernel<<<Bz * Ss, 256>>>();
    poolT_kernel<<<dim3(512, 2), 256>>>();
    wqkT_kernel<<<8, 128>>>(wqk_w);
    proj_mma_kernel<<<dim3(512, 2, 2), 256, PROJ_SMEM>>>(wqk_b);
    temp_kernel<<<512, 256>>>(wp_w, wp_b);
    scores_softmax_kernel<<<dim3(512, 4), 256, SS_SMEM>>>();
    att_mma_kernel<<<dim3(512, 2), 256, ATT_SMEM>>>(x, out);
}